// round 14
// baseline (speedup 1.0000x reference)
#include <cuda_runtime.h>
#include <cuda_bf16.h>
#include <cuda_fp16.h>
#include <cstdint>

#define BATCH 16
#define NTOK  1024
#define CDIM  256
#define NTHREADS 256
#define NSTAGE 3
#define SLAB_F 16384                    // split slab: 128 rows x 128B
#define SLAB_H 8192                     // single-fp16 slab: 128 rows x 64B
#define SMEM_3T (NSTAGE*2*SLAB_F + 4096)   // ring 96KB + mbar (zsm overlays ring)
#define SMEM_AV (NSTAGE*2*SLAB_H + 4096)   // ring 48KB + mbar + ss
#define SMEM_1T (NSTAGE*2*SLAB_H + 1024)

// ---------------------------------------------------------------------------
// Split tiled format: rows in tiles of 128; tile t, k-slab s (32 k) is a
// contiguous 16KB smem image: row r at r*128, chunk cc at (cc^(r&7))*16;
// chunks 0-3 hi, 4-7 lo (addr = hi ^ 64). fp16 pairs.
// Single-fp16 format: 8KB slabs, row r at r*64, chunk cc at (cc^((r>>1)&3))*16.
// ---------------------------------------------------------------------------
__device__ __align__(128) char g_xs  [16384*1024];      // x    fp16 split
__device__ __align__(128) char g_wvs [256*1024];        // Wv   fp16 split
__device__ __align__(128) char g_mts [256*1024];        // Mt = (Wq^T Wk)^T [e][c], fp16 split
__device__ __align__(128) char g_qms [16384*1024];      // qm = x·M, fp16 split
__device__ __align__(128) char g_vts [16*256*2048];     // v^T  fp16 single
__device__ __align__(128) char g_ots [16*256*2048];     // o^T  fp16 single
__device__ __align__(128) char g_attns[(size_t)16384*2048]; // attn_norm fp16 single
__device__ __align__(128) char g_wpts[1024*2048];       // Wp^T fp16 single
__device__ float g_zp[BATCH*8*NTOK];                    // per (b, n-tile, tok) exp sums
__device__ float g_w[BATCH*NTOK];                       // w_j = x_j . (Wk^T bq)
__device__ float g_beta[256];
__device__ float g_zero[256];

// ---------------------------------------------------------------------------
__device__ __forceinline__ uint32_t smem_u32(const void* p){
    uint32_t a;
    asm("{ .reg .u64 t; cvta.to.shared.u64 t, %1; cvt.u32.u64 %0, t; }" : "=r"(a) : "l"(p));
    return a;
}
__device__ __forceinline__ void ldsm4(uint32_t* r, uint32_t addr){
    asm volatile("ldmatrix.sync.aligned.m8n8.x4.shared.b16 {%0,%1,%2,%3}, [%4];"
        : "=r"(r[0]), "=r"(r[1]), "=r"(r[2]), "=r"(r[3]) : "r"(addr));
}
__device__ __forceinline__ void mma_f16(float* d, const uint32_t* a, const uint32_t* b){
    asm volatile("mma.sync.aligned.m16n8k16.row.col.f32.f16.f16.f32 "
        "{%0,%1,%2,%3}, {%4,%5,%6,%7}, {%8,%9}, {%0,%1,%2,%3};"
        : "+f"(d[0]), "+f"(d[1]), "+f"(d[2]), "+f"(d[3])
        : "r"(a[0]), "r"(a[1]), "r"(a[2]), "r"(a[3]), "r"(b[0]), "r"(b[1]));
}
__device__ __forceinline__ void split2h(float v0, float v1, __half2& h, __half2& l){
    h = __floats2half2_rn(v0, v1);
    l = __floats2half2_rn(v0 - __half2float(__low2half(h)),
                          v1 - __half2float(__high2half(h)));
}
template<class T> __device__ __forceinline__ uint32_t b2u(T v){
    uint32_t u; memcpy(&u, &v, 4); return u;
}
template<class T> __device__ __forceinline__ uint16_t b2s(T v){
    uint16_t u; memcpy(&u, &v, 2); return u;
}
__device__ __forceinline__ uint32_t h2mul(uint32_t a, uint32_t s){
    __half2 x, y; memcpy(&x, &a, 4); memcpy(&y, &s, 4);
    __half2 r = __hmul2(x, y); uint32_t u; memcpy(&u, &r, 4); return u;
}

// global tiled-format offsets (producers)
__device__ __forceinline__ size_t sbf_off(long tile, int nslab, int r, int k){
    int cc = (k & 31) >> 3;
    return ((size_t)(tile * nslab + (k >> 5)) << 14)
         + (size_t)(r * 128) + (size_t)(((cc ^ (r & 7)) << 4) + (k & 7) * 2);
}
__device__ __forceinline__ size_t h16_off(long tile, int nslab, int r, int k){
    int cc = (k & 31) >> 3;
    return ((size_t)(tile * nslab + (k >> 5)) << 13)
         + (size_t)(r * 64) + (size_t)(((cc ^ ((r >> 1) & 3)) << 4) + (k & 7) * 2);
}
// local (within stage region) offsets
__device__ __forceinline__ int loc_f(int r, int k){
    int cc = (k & 31) >> 3;
    return ((k >> 5) << 14) + r * 128 + ((cc ^ (r & 7)) << 4) + (k & 7) * 2;
}
__device__ __forceinline__ int loc_h(int r, int k){
    int cc = (k & 31) >> 3;
    return ((k >> 5) << 13) + r * 64 + ((cc ^ ((r >> 1) & 3)) << 4) + (k & 7) * 2;
}

#define MBAR_INIT(mb,c)  asm volatile("mbarrier.init.shared.b64 [%0], %1;" :: "r"(mb), "r"((uint32_t)(c)) : "memory")
#define MBAR_EXPECT(mb,n) asm volatile("mbarrier.arrive.expect_tx.shared.b64 _, [%0], %1;" :: "r"(mb), "r"((uint32_t)(n)) : "memory")
#define BULK_G2S(dst,src,n,mb) asm volatile("cp.async.bulk.shared::cta.global.mbarrier::complete_tx::bytes [%0], [%1], %2, [%3];" :: "r"(dst), "l"(src), "r"((uint32_t)(n)), "r"(mb) : "memory")
#define BULK_S2G(dst,src,n) asm volatile("cp.async.bulk.global.shared::cta.bulk_group [%0], [%1], %2;" :: "l"(dst), "r"(src), "r"((uint32_t)(n)) : "memory")
#define BULK_COMMIT() asm volatile("cp.async.bulk.commit_group;" ::: "memory")
#define BULK_WAIT0()  asm volatile("cp.async.bulk.wait_group 0;" ::: "memory")
#define FENCE_ASYNC() asm volatile("fence.proxy.async.shared::cta;" ::: "memory")

#define MBAR_WAIT(mb, par) do { \
    uint32_t _m = (uint32_t)(mb), _p = (uint32_t)(par), _d; \
    asm volatile("{\n\t.reg .pred p;\n\t" \
        "mbarrier.try_wait.parity.acquire.cta.shared::cta.b64 p, [%1], %2;\n\t" \
        "selp.b32 %0, 1, 0, p;\n\t}" : "=r"(_d) : "r"(_m), "r"(_p) : "memory"); \
    if (!_d) { \
        asm volatile("{\n\t.reg .pred P1;\n\t" \
            "WL_%=:\n\t" \
            "mbarrier.try_wait.parity.acquire.cta.shared::cta.b64 P1, [%0], %1, 0x989680;\n\t" \
            "@P1 bra.uni WD_%=;\n\t" \
            "bra.uni WL_%=;\n\t" \
            "WD_%=:\n\t}" :: "r"(_m), "r"(_p) : "memory"); \
    } \
} while(0)

// ---------------------------------------------------------------------------
// 3-term fp16 compute (split A, split B). CTA 128x128, warps 2(M)x4(N).
// ---------------------------------------------------------------------------
__device__ __forceinline__ void compute_slab3(char* buf, float acc[4][4][4])
{
    int tid = threadIdx.x, lane = tid & 31, wid = tid >> 5;
    uint32_t sA = smem_u32(buf), sB = sA + SLAB_F;
    int mw = (wid & 1) * 64, nw = (wid >> 1) * 32;
    int arow = lane & 15, ahalf = lane >> 4;
    int brow = (lane & 7) + ((lane >> 4) & 1) * 8, bhalf = (lane >> 3) & 1;

#pragma unroll
    for (int ks = 0; ks < 2; ++ks) {
        uint32_t bh[8], bl[8];
#pragma unroll
        for (int nj = 0; nj < 2; ++nj) {
            int r = nw + nj * 16 + brow;
            int c = ks * 2 + bhalf;
            ldsm4(bh + nj * 4, sB + r * 128 + (((c    ) ^ (r & 7)) << 4));
            ldsm4(bl + nj * 4, sB + r * 128 + (((c + 4) ^ (r & 7)) << 4));
        }
#pragma unroll
        for (int mi = 0; mi < 4; ++mi) {
            int r = mw + mi * 16 + arow;
            int c = ks * 2 + ahalf;
            uint32_t ah[4], al[4];
            ldsm4(ah, sA + r * 128 + (((c    ) ^ (r & 7)) << 4));
            ldsm4(al, sA + r * 128 + (((c + 4) ^ (r & 7)) << 4));
#pragma unroll
            for (int j = 0; j < 4; ++j) {
                const uint32_t* bhf = &bh[(j >> 1) * 4 + (j & 1) * 2];
                const uint32_t* blf = &bl[(j >> 1) * 4 + (j & 1) * 2];
                float* d = acc[mi][j];
                mma_f16(d, ah, bhf);
                mma_f16(d, al, bhf);
                mma_f16(d, ah, blf);
            }
        }
    }
}

// ---------------------------------------------------------------------------
// 1-term fp16 compute (single A, single B; 64B rows). Optional A-frag scale.
// ---------------------------------------------------------------------------
template<bool SCALE>
__device__ __forceinline__ void compute_slab1(char* buf, float acc[4][4][4],
        const __half* __restrict__ ss)
{
    int tid = threadIdx.x, lane = tid & 31, wid = tid >> 5;
    uint32_t sA = smem_u32(buf), sB = sA + SLAB_H;
    int mw = (wid & 1) * 64, nw = (wid >> 1) * 32;
    int arow = lane & 15, ahalf = lane >> 4;
    int brow = (lane & 7) + ((lane >> 4) & 1) * 8, bhalf = (lane >> 3) & 1;
    int r0 = lane >> 2;

    uint32_t sv0[4], sv1[4];
    if (SCALE) {
#pragma unroll
        for (int mi = 0; mi < 4; ++mi) {
            int rr = mw + mi * 16 + r0;
            sv0[mi] = b2u(__half2half2(ss[rr]));
            sv1[mi] = b2u(__half2half2(ss[rr + 8]));
        }
    }

#pragma unroll
    for (int ks = 0; ks < 2; ++ks) {
        uint32_t bh[8];
#pragma unroll
        for (int nj = 0; nj < 2; ++nj) {
            int r = nw + nj * 16 + brow;
            int c = ks * 2 + bhalf;
            ldsm4(bh + nj * 4, sB + r * 64 + ((c ^ ((r >> 1) & 3)) << 4));
        }
#pragma unroll
        for (int mi = 0; mi < 4; ++mi) {
            int r = mw + mi * 16 + arow;
            int c = ks * 2 + ahalf;
            uint32_t ah[4];
            ldsm4(ah, sA + r * 64 + ((c ^ ((r >> 1) & 3)) << 4));
            if (SCALE) {
                ah[0] = h2mul(ah[0], sv0[mi]);
                ah[2] = h2mul(ah[2], sv0[mi]);
                ah[1] = h2mul(ah[1], sv1[mi]);
                ah[3] = h2mul(ah[3], sv1[mi]);
            }
#pragma unroll
            for (int j = 0; j < 4; ++j)
                mma_f16(acc[mi][j], ah, &bh[(j >> 1) * 4 + (j & 1) * 2]);
        }
    }
}

// ---------------------------------------------------------------------------
// mbarrier setup (once per kernel) + persistent-capable mainloop.
// Stage of global slab g = g % NSTAGE; parity = (g / NSTAGE) & 1. Callers
// pass c0 = cumulative slab count so the ring continues across tiles.
// ---------------------------------------------------------------------------
__device__ __forceinline__ uint32_t mbar_setup(char* smem, int off)
{
    uint32_t mb = smem_u32(smem + off);
    if (threadIdx.x == 0) {
        MBAR_INIT(mb, 1); MBAR_INIT(mb + 8, 1); MBAR_INIT(mb + 16, 1);
        FENCE_ASYNC();
    }
    __syncthreads();
    return mb;
}

template<int NC, int MODE>   // MODE 1: fp16 3-term split; MODE 3: fp16 1-term
__device__ __forceinline__ void gemm_bulk(const char* __restrict__ A,
                                          const char* __restrict__ B,
                                          char* smem, uint32_t mb, int c0,
                                          float acc[4][4][4],
                                          const __half* __restrict__ ss = nullptr)
{
    constexpr int SL  = (MODE == 3) ? SLAB_H : SLAB_F;
    constexpr int STG = 2 * SL;
    int tid = threadIdx.x;
    if (tid == 0) {
#pragma unroll
        for (int s2 = 0; s2 < NSTAGE - 1; ++s2) {
            int st = (c0 + s2) % NSTAGE;
            uint32_t m = mb + 8 * st;
            uint32_t d = smem_u32(smem + st * STG);
            MBAR_EXPECT(m, STG);
            BULK_G2S(d,      A + (size_t)s2 * SL, SL, m);
            BULK_G2S(d + SL, B + (size_t)s2 * SL, SL, m);
        }
    }
#pragma unroll 4
    for (int c = 0; c < NC; ++c) {
        int g = c0 + c, s = g % NSTAGE, par = (g / NSTAGE) & 1;
        MBAR_WAIT(mb + 8 * s, par);
        __syncthreads();
        if (tid == 0 && c + NSTAGE - 1 < NC) {
            int sn = (g + NSTAGE - 1) % NSTAGE;
            uint32_t m = mb + 8 * sn;
            uint32_t d = smem_u32(smem + sn * STG);
            MBAR_EXPECT(m, STG);
            BULK_G2S(d,      A + (size_t)(c + NSTAGE - 1) * SL, SL, m);
            BULK_G2S(d + SL, B + (size_t)(c + NSTAGE - 1) * SL, SL, m);
        }
        if (MODE == 3) {
            if (ss) compute_slab1<true >(smem + s * STG, acc, ss + (c >> 2) * 128);
            else    compute_slab1<false>(smem + s * STG, acc, nullptr);
        } else {
            compute_slab3(smem + s * STG, acc);
        }
    }
}

// drain a staged 4-slab region to global
template<int SL>
__device__ __forceinline__ void stage_drain(char* smem, char* dst)
{
    __syncthreads();
    if (threadIdx.x == 0) {
        FENCE_ASYNC();
#pragma unroll
        for (int sl = 0; sl < 4; ++sl)
            BULK_S2G(dst + sl * SL, smem_u32(smem + sl * SL), SL);
        BULK_COMMIT();
        BULK_WAIT0();
    }
}

// ---------------------------------------------------------------------------
// Epilogues. Frag: d0,d1 -> (row=lane>>2, col=(lane&3)*2+e), d2,d3 row+8.
// ---------------------------------------------------------------------------
__device__ __forceinline__ void epi_f32(const float acc[4][4][4],
        float* __restrict__ Cg, int ldc)
{
    int tid = threadIdx.x, lane = tid & 31, wid = tid >> 5;
    int row0 = (wid & 1) * 64 + (lane >> 2), col0 = (wid >> 1) * 32 + (lane & 3) * 2;
#pragma unroll
    for (int mi = 0; mi < 4; ++mi)
#pragma unroll
        for (int j = 0; j < 4; ++j) {
            int c = col0 + j * 8;
#pragma unroll
            for (int h = 0; h < 2; ++h) {
                int r = row0 + mi * 16 + h * 8;
                *reinterpret_cast<float2*>(Cg + (long)r * ldc + c) =
                    make_float2(acc[mi][j][h * 2], acc[mi][j][h * 2 + 1]);
            }
        }
}

// qm: fp16 split normal; 64KB stage at smem base.
__device__ __forceinline__ void epi_split_h(const float acc[4][4][4],
        char* smem, char* dst, const float* __restrict__ bias)
{
    int tid = threadIdx.x, lane = tid & 31, wid = tid >> 5;
    int rw0 = (wid & 1) * 64 + (lane >> 2), cw0 = (wid >> 1) * 32 + (lane & 3) * 2;
    __syncthreads();
#pragma unroll
    for (int mi = 0; mi < 4; ++mi)
#pragma unroll
        for (int j = 0; j < 4; ++j) {
            int c = cw0 + j * 8;
            float b0 = bias[c], b1 = bias[c + 1];
#pragma unroll
            for (int h = 0; h < 2; ++h) {
                int r = rw0 + mi * 16 + h * 8;
                __half2 hh, ll;
                split2h(acc[mi][j][h * 2] + b0, acc[mi][j][h * 2 + 1] + b1, hh, ll);
                int off = loc_f(r, c);
                *reinterpret_cast<uint32_t*>(smem + off)        = b2u(hh);
                *reinterpret_cast<uint32_t*>(smem + (off ^ 64)) = b2u(ll);
            }
        }
    stage_drain<SLAB_F>(smem, dst);
}

// transposed single-fp16 (v^T with bias, o^T without); 32KB stage.
__device__ __forceinline__ void epi_t_h16(const float acc[4][4][4],
        char* smem, char* dst, const float* __restrict__ bias)
{
    int tid = threadIdx.x, lane = tid & 31, wid = tid >> 5;
    int rw0 = (wid & 1) * 64 + (lane >> 2), cw0 = (wid >> 1) * 32 + (lane & 3) * 2;
    __syncthreads();
#pragma unroll
    for (int mi = 0; mi < 4; ++mi)
#pragma unroll
        for (int j = 0; j < 4; ++j)
#pragma unroll
            for (int h = 0; h < 2; ++h) {
                int m = rw0 + mi * 16 + h * 8;
#pragma unroll
                for (int e = 0; e < 2; ++e) {
                    int n = cw0 + j * 8 + e;
                    float v = acc[mi][j][h * 2 + e] + (bias ? bias[n] : 0.0f);
                    *reinterpret_cast<uint16_t*>(smem + loc_h(n, m)) = b2s(__float2half(v));
                }
            }
    stage_drain<SLAB_H>(smem, dst);
}

// attn: exp(acc + w_col), per-tile normalize, single fp16 + partial sums.
// Stage 32KB at smem base; zsm overlays ring at +32KB (ring is drained here).
__device__ __forceinline__ void epi_attn(const float acc[4][4][4], char* smem,
        char* dst, const float* __restrict__ wcol, float* __restrict__ zp_out)
{
    int tid = threadIdx.x, lane = tid & 31, wid = tid >> 5;
    int rw0 = (wid & 1) * 64 + (lane >> 2), cw0 = (wid >> 1) * 32 + (lane & 3) * 2;
    float* zsm = reinterpret_cast<float*>(smem + 4 * SLAB_H);
    __syncthreads();

    float wc[8];
#pragma unroll
    for (int j = 0; j < 4; ++j) {
        wc[j * 2]     = wcol[cw0 + j * 8];
        wc[j * 2 + 1] = wcol[cw0 + j * 8 + 1];
    }

    float ex[4][4][4];
#pragma unroll
    for (int mi = 0; mi < 4; ++mi) {
#pragma unroll
        for (int h = 0; h < 2; ++h) {
            int r = rw0 + mi * 16 + h * 8;
            float rs = 0.0f;
#pragma unroll
            for (int j = 0; j < 4; ++j) {
                float e0 = __expf(acc[mi][j][h * 2]     + wc[j * 2]);
                float e1 = __expf(acc[mi][j][h * 2 + 1] + wc[j * 2 + 1]);
                ex[mi][j][h * 2] = e0; ex[mi][j][h * 2 + 1] = e1;
                rs += e0 + e1;
            }
            rs += __shfl_xor_sync(0xffffffffu, rs, 1);
            rs += __shfl_xor_sync(0xffffffffu, rs, 2);
            if ((lane & 3) == 0)
                zsm[(wid >> 1) * 128 + r] = rs;
        }
    }
    __syncthreads();
    if (tid < 128)
        zp_out[tid] = zsm[tid] + zsm[128 + tid] + zsm[256 + tid] + zsm[384 + tid];
#pragma unroll
    for (int mi = 0; mi < 4; ++mi)
#pragma unroll
        for (int h = 0; h < 2; ++h) {
            int r = rw0 + mi * 16 + h * 8;
            float inv = 1.0f / (zsm[r] + zsm[128 + r] + zsm[256 + r] + zsm[384 + r]);
#pragma unroll
            for (int j = 0; j < 4; ++j) {
                int c = cw0 + j * 8;
                __half2 hv = __floats2half2_rn(ex[mi][j][h * 2] * inv,
                                               ex[mi][j][h * 2 + 1] * inv);
                *reinterpret_cast<uint32_t*>(smem + loc_h(r, c)) = b2u(hv);
            }
        }
    stage_drain<SLAB_H>(smem, dst);
}

// ---------------------------------------------------------------------------
// Prep: Wv conv (0..63) | Wp^T single fp16 (64..1087) | Mt tiles (1088..1103)
//       | beta (1104)
// ---------------------------------------------------------------------------
__global__ void __launch_bounds__(NTHREADS) prep_kernel(
        const float* __restrict__ Wq, const float* __restrict__ Wk,
        const float* __restrict__ Wv, const float* __restrict__ Wp,
        const float* __restrict__ bq)
{
    int bid = blockIdx.x, tid = threadIdx.x;
    if (bid < 64) {
        long i = (long)bid * NTHREADS + tid;
        float4 v = reinterpret_cast<const float4*>(Wv)[i];
        long e = i * 4;
        int r = (int)(e >> 8), k = (int)(e & 255);
        size_t off = sbf_off(r >> 7, 8, r & 127, k);
        __half2 h0, l0, h1, l1;
        split2h(v.x, v.y, h0, l0);
        split2h(v.z, v.w, h1, l1);
        *reinterpret_cast<uint2*>(g_wvs + off)        = make_uint2(b2u(h0), b2u(h1));
        *reinterpret_cast<uint2*>(g_wvs + (off ^ 64)) = make_uint2(b2u(l0), b2u(l1));
    } else if (bid < 1088) {
        __shared__ float t[32][33];
        int b2 = bid - 64;
        int h = b2 >> 5, n0 = (b2 & 31) * 32;
        int tx = tid & 31, ty = tid >> 5;
        const float* src = Wp + (long)h * 32768 + (long)n0 * 32;
#pragma unroll
        for (int i = 0; i < 4; ++i) t[ty + i * 8][tx] = src[(ty + i * 8) * 32 + tx];
        __syncthreads();
#pragma unroll
        for (int i = 0; i < 4; ++i) {
            int w = ty + i * 8;
            int p = h * 32 + w, n = n0 + tx;
            *reinterpret_cast<uint16_t*>(g_wpts + h16_off(p >> 7, 32, p & 127, n)) =
                b2s(__float2half(t[tx][w]));
        }
    } else if (bid < 1104) {
        __shared__ float As[32][64], Bs[32][64];
        int mt = bid - 1088;
        int e0 = (mt >> 2) * 64, c0 = (mt & 3) * 64;
        int tx = tid & 15, ty = tid >> 4;
        float acc[4][4] = {};
        for (int k0 = 0; k0 < 256; k0 += 32) {
            for (int i = tid; i < 2048; i += NTHREADS) {
                int dd = i >> 6, ee = i & 63;
                As[dd][ee] = Wk[(long)(k0 + dd) * 256 + e0 + ee];
                Bs[dd][ee] = Wq[(long)(k0 + dd) * 256 + c0 + ee];
            }
            __syncthreads();
#pragma unroll 8
            for (int dd = 0; dd < 32; ++dd) {
                float a[4], b[4];
#pragma unroll
                for (int i = 0; i < 4; ++i) { a[i] = As[dd][ty * 4 + i]; b[i] = Bs[dd][tx * 4 + i]; }
#pragma unroll
                for (int i = 0; i < 4; ++i)
#pragma unroll
                    for (int j = 0; j < 4; ++j) acc[i][j] += a[i] * b[j];
            }
            __syncthreads();
        }
#pragma unroll
        for (int i = 0; i < 4; ++i)
#pragma unroll
            for (int j = 0; j < 4; ++j) {
                int e = e0 + ty * 4 + i, c = c0 + tx * 4 + j;
                __half hb = __float2half(acc[i][j]);
                __half lb = __float2half(acc[i][j] - __half2float(hb));
                size_t off = sbf_off(e >> 7, 8, e & 127, c);
                *reinterpret_cast<uint16_t*>(g_mts + off)        = b2s(hb);
                *reinterpret_cast<uint16_t*>(g_mts + (off ^ 64)) = b2s(lb);
            }
    } else {
        int c = tid;
        float acc = 0.0f;
        for (int d = 0; d < 256; ++d) acc += Wk[(long)d * 256 + c] * bq[d];
        g_beta[c] = acc;
    }
}

// x conv (0..4095) + w vector (4096..6143)
__global__ void __launch_bounds__(NTHREADS) xconv_kernel(const float* __restrict__ src)
{
    int bid = blockIdx.x, tid = threadIdx.x;
    if (bid < 4096) {
        long i = (long)bid * NTHREADS + tid;
        float4 v = reinterpret_cast<const float4*>(src)[i];
        long e = i * 4;
        int r = (int)(e >> 8), k = (int)(e & 255);
        size_t off = sbf_off(r >> 7, 8, r & 127, k);
        __half2 h0, l0, h1, l1;
        split2h(v.x, v.y, h0, l0);
        split2h(v.z, v.w, h1, l1);
        *reinterpret_cast<uint2*>(g_xs + off)        = make_uint2(b2u(h0), b2u(h1));
        *reinterpret_cast<uint2*>(g_xs + (off ^ 64)) = make_uint2(b2u(l0), b2u(l1));
    } else {
        int row = (bid - 4096) * 8 + (tid >> 5);
        int lane = tid & 31;
        float p = 0.0f;
#pragma unroll
        for (int e = 0; e < 8; ++e)
            p += src[(long)row * 256 + lane + e * 32] * g_beta[lane + e * 32];
#pragma unroll
        for (int o = 16; o; o >>= 1) p += __shfl_xor_sync(0xffffffffu, p, o);
        if (!lane) g_w[row] = p;
    }
}

// ---------------------------------------------------------------------------
// Stage 1: proj, persistent. grid (256): cta = (m-tile << 1) | sel;
// each CTA does both n-tiles (A reused, ring continues).
// ---------------------------------------------------------------------------
__global__ void __launch_bounds__(NTHREADS, 2)
proj_kernel(const float* __restrict__ bv)
{
    extern __shared__ char smem[];
    int sel = blockIdx.x & 1;
    long mt = blockIdx.x >> 1;                    // 0..127
    uint32_t mb = mbar_setup(smem, NSTAGE * 2 * SLAB_F);
    const char* Ap = g_xs + (size_t)mt * 8 * SLAB_F;
    const char* Bb = (sel == 0) ? g_mts : g_wvs;

    for (int nn = 0; nn < 2; ++nn) {
        float acc[4][4][4] = {};
        gemm_bulk<8, 1>(Ap, Bb + (size_t)nn * 8 * SLAB_F, smem, mb, nn * 8, acc);
        if (sel == 0) {
            char* dst = g_qms + ((size_t)mt * 8 + nn * 4) * SLAB_F;
            epi_split_h(acc, smem, dst, g_zero + nn * 128);
        } else {
            int b = (int)(mt >> 3), mtb = (int)(mt & 7);
            char* dst = g_vts + ((size_t)(b * 2 + nn) * 32 + mtb * 4) * SLAB_H;
            epi_t_h16(acc, smem, dst, bv + nn * 128);
        }
    }
}

// ---------------------------------------------------------------------------
// Stage 2: scores, persistent. grid (256): cta = b*16 + m-tile*2 + half;
// each CTA does 4 n-tiles of the same (b, m) (A reused, ring continues).
// ---------------------------------------------------------------------------
__global__ void __launch_bounds__(NTHREADS, 2) scores_kernel()
{
    extern __shared__ char smem[];
    int b = blockIdx.x >> 4, q = blockIdx.x & 15;
    int mt = q >> 1, half = q & 1;
    uint32_t mb = mbar_setup(smem, NSTAGE * 2 * SLAB_F);
    const char* Ap = g_qms + (size_t)(b * 8 + mt) * 8 * SLAB_F;

    for (int i = 0; i < 4; ++i) {
        int nt = half * 4 + i;
        float acc[4][4][4] = {};
        gemm_bulk<8, 1>(Ap, g_xs + (size_t)(b * 8 + nt) * 8 * SLAB_F,
                        smem, mb, i * 8, acc);
        char* dst = g_attns + ((size_t)(b * 8 + mt) * 32 + nt * 4) * SLAB_H;
        epi_attn(acc, smem, dst, g_w + (long)b * NTOK + nt * 128,
                 g_zp + ((long)b * 8 + nt) * NTOK + mt * 128);
    }
}

// ---------------------------------------------------------------------------
// Stage 3: o^T, fp16 1-term with per-tile A rescale. grid (2, 8, 16)
// ---------------------------------------------------------------------------
__global__ void __launch_bounds__(NTHREADS, 2) av_kernel()
{
    extern __shared__ char smem[];
    int c0 = blockIdx.x * 128, tok0 = blockIdx.y * 128, b = blockIdx.z;
    uint32_t mb = mbar_setup(smem, NSTAGE * 2 * SLAB_H);
    __half* ss = reinterpret_cast<__half*>(smem + NSTAGE * 2 * SLAB_H + 64);
    if (threadIdx.x < 128) {
        float z[8], Z = 0.0f;
#pragma unroll
        for (int t = 0; t < 8; ++t) {
            z[t] = g_zp[((long)b * 8 + t) * NTOK + tok0 + threadIdx.x];
            Z += z[t];
        }
        float invZ = 1.0f / Z;
#pragma unroll
        for (int t = 0; t < 8; ++t)
            ss[t * 128 + threadIdx.x] = __float2half(z[t] * invZ);
    }
    float acc[4][4][4] = {};
    gemm_bulk<32, 3>(g_attns + (size_t)((b * NTOK + tok0) >> 7) * 32 * SLAB_H,
                     g_vts   + (size_t)(b * 2 + (c0 >> 7))      * 32 * SLAB_H,
                     smem, mb, 0, acc, ss);
    char* dst = g_ots + ((size_t)(b * 2 + (c0 >> 7)) * 32 + (tok0 >> 5)) * SLAB_H;
    epi_t_h16(acc, smem, dst, nullptr);
}

// ---------------------------------------------------------------------------
// Stage 4: z = Wp^T o, fp16 1-term. grid (2, 8, 16)
// ---------------------------------------------------------------------------
__global__ void __launch_bounds__(NTHREADS, 2) final_kernel(float* __restrict__ z)
{
    extern __shared__ char smem[];
    int c0 = blockIdx.x * 128, p0 = blockIdx.y * 128, b = blockIdx.z;
    uint32_t mb = mbar_setup(smem, NSTAGE * 2 * SLAB_H);
    float acc[4][4][4] = {};
    gemm_bulk<32, 3>(g_wpts + (size_t)(p0 >> 7) * 32 * SLAB_H,
                     g_ots  + (size_t)(b * 2 + (c0 >> 7)) * 32 * SLAB_H,
                     smem, mb, 0, acc);
    epi_f32(acc, z + ((long)b * NTOK + p0) * CDIM + c0, CDIM);
}

// ---------------------------------------------------------------------------
extern "C" void kernel_launch(void* const* d_in, const int* in_sizes, int n_in,
                              void* d_out, int out_size)
{
    const float* x  = (const float*)d_in[0];
    const float* Wq = (const float*)d_in[1];
    const float* bq = (const float*)d_in[2];
    const float* Wk = (const float*)d_in[3];
    const float* Wv = (const float*)d_in[5];
    const float* bv = (const float*)d_in[6];
    const float* Wp = (const float*)d_in[7];
    float* out = (float*)d_out;

    cudaFuncSetAttribute(proj_kernel,   cudaFuncAttributeMaxDynamicSharedMemorySize, SMEM_3T);
    cudaFuncSetAttribute(scores_kernel, cudaFuncAttributeMaxDynamicSharedMemorySize, SMEM_3T);
    cudaFuncSetAttribute(av_kernel,     cudaFuncAttributeMaxDynamicSharedMemorySize, SMEM_AV);
    cudaFuncSetAttribute(final_kernel,  cudaFuncAttributeMaxDynamicSharedMemorySize, SMEM_1T);

    prep_kernel <<<dim3(1105), NTHREADS>>>(Wq, Wk, Wv, Wp, bq);            // 1
    xconv_kernel<<<dim3(6144), NTHREADS>>>(x);                             // 2
    proj_kernel  <<<dim3(256), NTHREADS, SMEM_3T>>>(bv);                   // 3
    scores_kernel<<<dim3(256), NTHREADS, SMEM_3T>>>();                     // 4 <- profiled
    av_kernel    <<<dim3(2, 8, 16), NTHREADS, SMEM_AV>>>();                // 5
    final_kernel <<<dim3(2, 8, 16), NTHREADS, SMEM_1T>>>(out);             // 6
}

// round 15
// speedup vs baseline: 1.0730x; 1.0730x over previous
#include <cuda_runtime.h>
#include <cuda_bf16.h>
#include <cuda_fp16.h>
#include <cstdint>

#define BATCH 16
#define NTOK  1024
#define CDIM  256
#define NTHREADS 256
#define NSTG_F 3                        // stages for split (32KB) kernels
#define NSTG_H 4                        // stages for 1-term (16KB) kernels
#define SLAB_F 16384                    // split slab: 128 rows x 128B
#define SLAB_H 8192                     // single-fp16 slab: 128 rows x 64B
#define SMEM_3T (NSTG_F*2*SLAB_F + 4096)   // ring 96KB + mbar (zsm overlays ring)
#define SMEM_AV (NSTG_H*2*SLAB_H + 4096)   // ring 64KB + mbar + ss
#define SMEM_1T (NSTG_H*2*SLAB_H + 1024)

// ---------------------------------------------------------------------------
// Split tiled format: rows in tiles of 128; tile t, k-slab s (32 k) is a
// contiguous 16KB smem image: row r at r*128, chunk cc at (cc^(r&7))*16;
// chunks 0-3 hi, 4-7 lo (addr = hi ^ 64). fp16 pairs.
// Single-fp16 format: 8KB slabs, row r at r*64, chunk cc at (cc^((r>>1)&3))*16.
// ---------------------------------------------------------------------------
__device__ __align__(128) char g_xs  [16384*1024];      // x    fp16 split
__device__ __align__(128) char g_wvs [256*1024];        // Wv   fp16 split
__device__ __align__(128) char g_mts [256*1024];        // Mt = (Wq^T Wk)^T [e][c], fp16 split
__device__ __align__(128) char g_qms [16384*1024];      // qm = x·M, fp16 split
__device__ __align__(128) char g_vts [16*256*2048];     // v^T  fp16 single
__device__ __align__(128) char g_ots [16*256*2048];     // o^T  fp16 single
__device__ __align__(128) char g_attns[(size_t)16384*2048]; // attn_norm fp16 single
__device__ __align__(128) char g_wpts[1024*2048];       // Wp^T fp16 single
__device__ float g_zp[BATCH*8*NTOK];                    // per (b, n-tile, tok) exp sums
__device__ float g_w[BATCH*NTOK];                       // w_j = x_j . (Wk^T bq)
__device__ float g_beta[256];
__device__ float g_zero[256];

// ---------------------------------------------------------------------------
__device__ __forceinline__ uint32_t smem_u32(const void* p){
    uint32_t a;
    asm("{ .reg .u64 t; cvta.to.shared.u64 t, %1; cvt.u32.u64 %0, t; }" : "=r"(a) : "l"(p));
    return a;
}
__device__ __forceinline__ void ldsm4(uint32_t* r, uint32_t addr){
    asm volatile("ldmatrix.sync.aligned.m8n8.x4.shared.b16 {%0,%1,%2,%3}, [%4];"
        : "=r"(r[0]), "=r"(r[1]), "=r"(r[2]), "=r"(r[3]) : "r"(addr));
}
__device__ __forceinline__ void mma_f16(float* d, const uint32_t* a, const uint32_t* b){
    asm volatile("mma.sync.aligned.m16n8k16.row.col.f32.f16.f16.f32 "
        "{%0,%1,%2,%3}, {%4,%5,%6,%7}, {%8,%9}, {%0,%1,%2,%3};"
        : "+f"(d[0]), "+f"(d[1]), "+f"(d[2]), "+f"(d[3])
        : "r"(a[0]), "r"(a[1]), "r"(a[2]), "r"(a[3]), "r"(b[0]), "r"(b[1]));
}
__device__ __forceinline__ void split2h(float v0, float v1, __half2& h, __half2& l){
    h = __floats2half2_rn(v0, v1);
    l = __floats2half2_rn(v0 - __half2float(__low2half(h)),
                          v1 - __half2float(__high2half(h)));
}
template<class T> __device__ __forceinline__ uint32_t b2u(T v){
    uint32_t u; memcpy(&u, &v, 4); return u;
}
template<class T> __device__ __forceinline__ uint16_t b2s(T v){
    uint16_t u; memcpy(&u, &v, 2); return u;
}
__device__ __forceinline__ uint32_t h2mul(uint32_t a, uint32_t s){
    __half2 x, y; memcpy(&x, &a, 4); memcpy(&y, &s, 4);
    __half2 r = __hmul2(x, y); uint32_t u; memcpy(&u, &r, 4); return u;
}

// global tiled-format offsets (producers)
__device__ __forceinline__ size_t sbf_off(long tile, int nslab, int r, int k){
    int cc = (k & 31) >> 3;
    return ((size_t)(tile * nslab + (k >> 5)) << 14)
         + (size_t)(r * 128) + (size_t)(((cc ^ (r & 7)) << 4) + (k & 7) * 2);
}
__device__ __forceinline__ size_t h16_off(long tile, int nslab, int r, int k){
    int cc = (k & 31) >> 3;
    return ((size_t)(tile * nslab + (k >> 5)) << 13)
         + (size_t)(r * 64) + (size_t)(((cc ^ ((r >> 1) & 3)) << 4) + (k & 7) * 2);
}
// local (within stage region) offsets
__device__ __forceinline__ int loc_f(int r, int k){
    int cc = (k & 31) >> 3;
    return ((k >> 5) << 14) + r * 128 + ((cc ^ (r & 7)) << 4) + (k & 7) * 2;
}
__device__ __forceinline__ int loc_h(int r, int k){
    int cc = (k & 31) >> 3;
    return ((k >> 5) << 13) + r * 64 + ((cc ^ ((r >> 1) & 3)) << 4) + (k & 7) * 2;
}

#define MBAR_INIT(mb,c)  asm volatile("mbarrier.init.shared.b64 [%0], %1;" :: "r"(mb), "r"((uint32_t)(c)) : "memory")
#define MBAR_EXPECT(mb,n) asm volatile("mbarrier.arrive.expect_tx.shared.b64 _, [%0], %1;" :: "r"(mb), "r"((uint32_t)(n)) : "memory")
#define BULK_G2S(dst,src,n,mb) asm volatile("cp.async.bulk.shared::cta.global.mbarrier::complete_tx::bytes [%0], [%1], %2, [%3];" :: "r"(dst), "l"(src), "r"((uint32_t)(n)), "r"(mb) : "memory")
#define BULK_S2G(dst,src,n) asm volatile("cp.async.bulk.global.shared::cta.bulk_group [%0], [%1], %2;" :: "l"(dst), "r"(src), "r"((uint32_t)(n)) : "memory")
#define BULK_COMMIT() asm volatile("cp.async.bulk.commit_group;" ::: "memory")
#define BULK_WAIT0()  asm volatile("cp.async.bulk.wait_group 0;" ::: "memory")
#define FENCE_ASYNC() asm volatile("fence.proxy.async.shared::cta;" ::: "memory")

#define MBAR_WAIT(mb, par) do { \
    uint32_t _m = (uint32_t)(mb), _p = (uint32_t)(par), _d; \
    asm volatile("{\n\t.reg .pred p;\n\t" \
        "mbarrier.try_wait.parity.acquire.cta.shared::cta.b64 p, [%1], %2;\n\t" \
        "selp.b32 %0, 1, 0, p;\n\t}" : "=r"(_d) : "r"(_m), "r"(_p) : "memory"); \
    if (!_d) { \
        asm volatile("{\n\t.reg .pred P1;\n\t" \
            "WL_%=:\n\t" \
            "mbarrier.try_wait.parity.acquire.cta.shared::cta.b64 P1, [%0], %1, 0x989680;\n\t" \
            "@P1 bra.uni WD_%=;\n\t" \
            "bra.uni WL_%=;\n\t" \
            "WD_%=:\n\t}" :: "r"(_m), "r"(_p) : "memory"); \
    } \
} while(0)

// ---------------------------------------------------------------------------
// 3-term fp16 compute (split A, split B). CTA 128x128, warps 2(M)x4(N).
// ---------------------------------------------------------------------------
__device__ __forceinline__ void compute_slab3(char* buf, float acc[4][4][4])
{
    int tid = threadIdx.x, lane = tid & 31, wid = tid >> 5;
    uint32_t sA = smem_u32(buf), sB = sA + SLAB_F;
    int mw = (wid & 1) * 64, nw = (wid >> 1) * 32;
    int arow = lane & 15, ahalf = lane >> 4;
    int brow = (lane & 7) + ((lane >> 4) & 1) * 8, bhalf = (lane >> 3) & 1;

#pragma unroll
    for (int ks = 0; ks < 2; ++ks) {
        uint32_t bh[8], bl[8];
#pragma unroll
        for (int nj = 0; nj < 2; ++nj) {
            int r = nw + nj * 16 + brow;
            int c = ks * 2 + bhalf;
            ldsm4(bh + nj * 4, sB + r * 128 + (((c    ) ^ (r & 7)) << 4));
            ldsm4(bl + nj * 4, sB + r * 128 + (((c + 4) ^ (r & 7)) << 4));
        }
#pragma unroll
        for (int mi = 0; mi < 4; ++mi) {
            int r = mw + mi * 16 + arow;
            int c = ks * 2 + ahalf;
            uint32_t ah[4], al[4];
            ldsm4(ah, sA + r * 128 + (((c    ) ^ (r & 7)) << 4));
            ldsm4(al, sA + r * 128 + (((c + 4) ^ (r & 7)) << 4));
#pragma unroll
            for (int j = 0; j < 4; ++j) {
                const uint32_t* bhf = &bh[(j >> 1) * 4 + (j & 1) * 2];
                const uint32_t* blf = &bl[(j >> 1) * 4 + (j & 1) * 2];
                float* d = acc[mi][j];
                mma_f16(d, ah, bhf);
                mma_f16(d, al, bhf);
                mma_f16(d, ah, blf);
            }
        }
    }
}

// ---------------------------------------------------------------------------
// 1-term fp16 compute (single A, single B; 64B rows). Optional A-frag scale.
// ---------------------------------------------------------------------------
template<bool SCALE>
__device__ __forceinline__ void compute_slab1(char* buf, float acc[4][4][4],
        const __half* __restrict__ ss)
{
    int tid = threadIdx.x, lane = tid & 31, wid = tid >> 5;
    uint32_t sA = smem_u32(buf), sB = sA + SLAB_H;
    int mw = (wid & 1) * 64, nw = (wid >> 1) * 32;
    int arow = lane & 15, ahalf = lane >> 4;
    int brow = (lane & 7) + ((lane >> 4) & 1) * 8, bhalf = (lane >> 3) & 1;
    int r0 = lane >> 2;

    uint32_t sv0[4], sv1[4];
    if (SCALE) {
#pragma unroll
        for (int mi = 0; mi < 4; ++mi) {
            int rr = mw + mi * 16 + r0;
            sv0[mi] = b2u(__half2half2(ss[rr]));
            sv1[mi] = b2u(__half2half2(ss[rr + 8]));
        }
    }

#pragma unroll
    for (int ks = 0; ks < 2; ++ks) {
        uint32_t bh[8];
#pragma unroll
        for (int nj = 0; nj < 2; ++nj) {
            int r = nw + nj * 16 + brow;
            int c = ks * 2 + bhalf;
            ldsm4(bh + nj * 4, sB + r * 64 + ((c ^ ((r >> 1) & 3)) << 4));
        }
#pragma unroll
        for (int mi = 0; mi < 4; ++mi) {
            int r = mw + mi * 16 + arow;
            int c = ks * 2 + ahalf;
            uint32_t ah[4];
            ldsm4(ah, sA + r * 64 + ((c ^ ((r >> 1) & 3)) << 4));
            if (SCALE) {
                ah[0] = h2mul(ah[0], sv0[mi]);
                ah[2] = h2mul(ah[2], sv0[mi]);
                ah[1] = h2mul(ah[1], sv1[mi]);
                ah[3] = h2mul(ah[3], sv1[mi]);
            }
#pragma unroll
            for (int j = 0; j < 4; ++j)
                mma_f16(acc[mi][j], ah, &bh[(j >> 1) * 4 + (j & 1) * 2]);
        }
    }
}

// ---------------------------------------------------------------------------
// Bulk-copy mainloop. MODE 1: fp16 3-term split (NST=3); MODE 3: 1-term (NST=4).
// ---------------------------------------------------------------------------
template<int NC, int MODE, int NST>
__device__ __forceinline__ void gemm_bulk(const char* __restrict__ A,
                                          const char* __restrict__ B,
                                          char* smem, float acc[4][4][4],
                                          const __half* __restrict__ ss = nullptr)
{
    constexpr int SL  = (MODE == 3) ? SLAB_H : SLAB_F;
    constexpr int STG = 2 * SL;
    uint32_t mb = smem_u32(smem + NST * STG);
    int tid = threadIdx.x;
    if (tid == 0) {
#pragma unroll
        for (int s = 0; s < NST; ++s) MBAR_INIT(mb + 8 * s, 1);
        FENCE_ASYNC();
    }
    __syncthreads();
    if (tid == 0) {
#pragma unroll
        for (int s = 0; s < NST - 1; ++s) {
            uint32_t m = mb + 8 * s;
            uint32_t d = smem_u32(smem + s * STG);
            MBAR_EXPECT(m, STG);
            BULK_G2S(d,      A + (size_t)s * SL, SL, m);
            BULK_G2S(d + SL, B + (size_t)s * SL, SL, m);
        }
    }
#pragma unroll 4
    for (int c = 0; c < NC; ++c) {
        int s = c % NST;
        MBAR_WAIT(mb + 8 * s, (c / NST) & 1);
        __syncthreads();
        int nc = c + NST - 1;
        if (tid == 0 && nc < NC) {
            int sn = nc % NST;
            uint32_t m = mb + 8 * sn;
            uint32_t d = smem_u32(smem + sn * STG);
            MBAR_EXPECT(m, STG);
            BULK_G2S(d,      A + (size_t)nc * SL, SL, m);
            BULK_G2S(d + SL, B + (size_t)nc * SL, SL, m);
        }
        if (MODE == 3) {
            if (ss) compute_slab1<true >(smem + s * STG, acc, ss + (c >> 2) * 128);
            else    compute_slab1<false>(smem + s * STG, acc, nullptr);
        } else {
            compute_slab3(smem + s * STG, acc);
        }
    }
}

// drain a staged 4-slab region to global
template<int SL>
__device__ __forceinline__ void stage_drain(char* smem, char* dst)
{
    __syncthreads();
    if (threadIdx.x == 0) {
        FENCE_ASYNC();
#pragma unroll
        for (int sl = 0; sl < 4; ++sl)
            BULK_S2G(dst + sl * SL, smem_u32(smem + sl * SL), SL);
        BULK_COMMIT();
        BULK_WAIT0();
    }
}

// ---------------------------------------------------------------------------
// Epilogues. Frag: d0,d1 -> (row=lane>>2, col=(lane&3)*2+e), d2,d3 row+8.
// ---------------------------------------------------------------------------
__device__ __forceinline__ void epi_f32(const float acc[4][4][4],
        float* __restrict__ Cg, int ldc)
{
    int tid = threadIdx.x, lane = tid & 31, wid = tid >> 5;
    int row0 = (wid & 1) * 64 + (lane >> 2), col0 = (wid >> 1) * 32 + (lane & 3) * 2;
#pragma unroll
    for (int mi = 0; mi < 4; ++mi)
#pragma unroll
        for (int j = 0; j < 4; ++j) {
            int c = col0 + j * 8;
#pragma unroll
            for (int h = 0; h < 2; ++h) {
                int r = row0 + mi * 16 + h * 8;
                *reinterpret_cast<float2*>(Cg + (long)r * ldc + c) =
                    make_float2(acc[mi][j][h * 2], acc[mi][j][h * 2 + 1]);
            }
        }
}

// qm: fp16 split normal; 64KB stage at smem base.
__device__ __forceinline__ void epi_split_h(const float acc[4][4][4],
        char* smem, char* dst, const float* __restrict__ bias)
{
    int tid = threadIdx.x, lane = tid & 31, wid = tid >> 5;
    int rw0 = (wid & 1) * 64 + (lane >> 2), cw0 = (wid >> 1) * 32 + (lane & 3) * 2;
    __syncthreads();
#pragma unroll
    for (int mi = 0; mi < 4; ++mi)
#pragma unroll
        for (int j = 0; j < 4; ++j) {
            int c = cw0 + j * 8;
            float b0 = bias[c], b1 = bias[c + 1];
#pragma unroll
            for (int h = 0; h < 2; ++h) {
                int r = rw0 + mi * 16 + h * 8;
                __half2 hh, ll;
                split2h(acc[mi][j][h * 2] + b0, acc[mi][j][h * 2 + 1] + b1, hh, ll);
                int off = loc_f(r, c);
                *reinterpret_cast<uint32_t*>(smem + off)        = b2u(hh);
                *reinterpret_cast<uint32_t*>(smem + (off ^ 64)) = b2u(ll);
            }
        }
    stage_drain<SLAB_F>(smem, dst);
}

// transposed single-fp16 (v^T with bias, o^T without); 32KB stage.
__device__ __forceinline__ void epi_t_h16(const float acc[4][4][4],
        char* smem, char* dst, const float* __restrict__ bias)
{
    int tid = threadIdx.x, lane = tid & 31, wid = tid >> 5;
    int rw0 = (wid & 1) * 64 + (lane >> 2), cw0 = (wid >> 1) * 32 + (lane & 3) * 2;
    __syncthreads();
#pragma unroll
    for (int mi = 0; mi < 4; ++mi)
#pragma unroll
        for (int j = 0; j < 4; ++j)
#pragma unroll
            for (int h = 0; h < 2; ++h) {
                int m = rw0 + mi * 16 + h * 8;
#pragma unroll
                for (int e = 0; e < 2; ++e) {
                    int n = cw0 + j * 8 + e;
                    float v = acc[mi][j][h * 2 + e] + (bias ? bias[n] : 0.0f);
                    *reinterpret_cast<uint16_t*>(smem + loc_h(n, m)) = b2s(__float2half(v));
                }
            }
    stage_drain<SLAB_H>(smem, dst);
}

// attn: exp(acc + w_col), per-tile normalize, single fp16 + partial sums.
// Stage 32KB at smem base; zsm overlays ring at +32KB (ring is drained here).
__device__ __forceinline__ void epi_attn(const float acc[4][4][4], char* smem,
        char* dst, const float* __restrict__ wcol, float* __restrict__ zp_out)
{
    int tid = threadIdx.x, lane = tid & 31, wid = tid >> 5;
    int rw0 = (wid & 1) * 64 + (lane >> 2), cw0 = (wid >> 1) * 32 + (lane & 3) * 2;
    float* zsm = reinterpret_cast<float*>(smem + 4 * SLAB_H);
    __syncthreads();

    float wc[8];
#pragma unroll
    for (int j = 0; j < 4; ++j) {
        wc[j * 2]     = wcol[cw0 + j * 8];
        wc[j * 2 + 1] = wcol[cw0 + j * 8 + 1];
    }

    float ex[4][4][4];
#pragma unroll
    for (int mi = 0; mi < 4; ++mi) {
#pragma unroll
        for (int h = 0; h < 2; ++h) {
            int r = rw0 + mi * 16 + h * 8;
            float rs = 0.0f;
#pragma unroll
            for (int j = 0; j < 4; ++j) {
                float e0 = __expf(acc[mi][j][h * 2]     + wc[j * 2]);
                float e1 = __expf(acc[mi][j][h * 2 + 1] + wc[j * 2 + 1]);
                ex[mi][j][h * 2] = e0; ex[mi][j][h * 2 + 1] = e1;
                rs += e0 + e1;
            }
            rs += __shfl_xor_sync(0xffffffffu, rs, 1);
            rs += __shfl_xor_sync(0xffffffffu, rs, 2);
            if ((lane & 3) == 0)
                zsm[(wid >> 1) * 128 + r] = rs;
        }
    }
    __syncthreads();
    if (tid < 128)
        zp_out[tid] = zsm[tid] + zsm[128 + tid] + zsm[256 + tid] + zsm[384 + tid];
#pragma unroll
    for (int mi = 0; mi < 4; ++mi)
#pragma unroll
        for (int h = 0; h < 2; ++h) {
            int r = rw0 + mi * 16 + h * 8;
            float inv = 1.0f / (zsm[r] + zsm[128 + r] + zsm[256 + r] + zsm[384 + r]);
#pragma unroll
            for (int j = 0; j < 4; ++j) {
                int c = cw0 + j * 8;
                __half2 hv = __floats2half2_rn(ex[mi][j][h * 2] * inv,
                                               ex[mi][j][h * 2 + 1] * inv);
                *reinterpret_cast<uint32_t*>(smem + loc_h(r, c)) = b2u(hv);
            }
        }
    stage_drain<SLAB_H>(smem, dst);
}

// ---------------------------------------------------------------------------
// Prep: Wv conv (0..63) | Wp^T single fp16 (64..1087) | Mt tiles (1088..1103)
//       | beta (1104)
// ---------------------------------------------------------------------------
__global__ void __launch_bounds__(NTHREADS) prep_kernel(
        const float* __restrict__ Wq, const float* __restrict__ Wk,
        const float* __restrict__ Wv, const float* __restrict__ Wp,
        const float* __restrict__ bq)
{
    int bid = blockIdx.x, tid = threadIdx.x;
    if (bid < 64) {
        long i = (long)bid * NTHREADS + tid;
        float4 v = reinterpret_cast<const float4*>(Wv)[i];
        long e = i * 4;
        int r = (int)(e >> 8), k = (int)(e & 255);
        size_t off = sbf_off(r >> 7, 8, r & 127, k);
        __half2 h0, l0, h1, l1;
        split2h(v.x, v.y, h0, l0);
        split2h(v.z, v.w, h1, l1);
        *reinterpret_cast<uint2*>(g_wvs + off)        = make_uint2(b2u(h0), b2u(h1));
        *reinterpret_cast<uint2*>(g_wvs + (off ^ 64)) = make_uint2(b2u(l0), b2u(l1));
    } else if (bid < 1088) {
        __shared__ float t[32][33];
        int b2 = bid - 64;
        int h = b2 >> 5, n0 = (b2 & 31) * 32;
        int tx = tid & 31, ty = tid >> 5;
        const float* src = Wp + (long)h * 32768 + (long)n0 * 32;
#pragma unroll
        for (int i = 0; i < 4; ++i) t[ty + i * 8][tx] = src[(ty + i * 8) * 32 + tx];
        __syncthreads();
#pragma unroll
        for (int i = 0; i < 4; ++i) {
            int w = ty + i * 8;
            int p = h * 32 + w, n = n0 + tx;
            *reinterpret_cast<uint16_t*>(g_wpts + h16_off(p >> 7, 32, p & 127, n)) =
                b2s(__float2half(t[tx][w]));
        }
    } else if (bid < 1104) {
        __shared__ float As[32][64], Bs[32][64];
        int mt = bid - 1088;
        int e0 = (mt >> 2) * 64, c0 = (mt & 3) * 64;
        int tx = tid & 15, ty = tid >> 4;
        float acc[4][4] = {};
        for (int k0 = 0; k0 < 256; k0 += 32) {
            for (int i = tid; i < 2048; i += NTHREADS) {
                int dd = i >> 6, ee = i & 63;
                As[dd][ee] = Wk[(long)(k0 + dd) * 256 + e0 + ee];
                Bs[dd][ee] = Wq[(long)(k0 + dd) * 256 + c0 + ee];
            }
            __syncthreads();
#pragma unroll 8
            for (int dd = 0; dd < 32; ++dd) {
                float a[4], b[4];
#pragma unroll
                for (int i = 0; i < 4; ++i) { a[i] = As[dd][ty * 4 + i]; b[i] = Bs[dd][tx * 4 + i]; }
#pragma unroll
                for (int i = 0; i < 4; ++i)
#pragma unroll
                    for (int j = 0; j < 4; ++j) acc[i][j] += a[i] * b[j];
            }
            __syncthreads();
        }
#pragma unroll
        for (int i = 0; i < 4; ++i)
#pragma unroll
            for (int j = 0; j < 4; ++j) {
                int e = e0 + ty * 4 + i, c = c0 + tx * 4 + j;
                __half hb = __float2half(acc[i][j]);
                __half lb = __float2half(acc[i][j] - __half2float(hb));
                size_t off = sbf_off(e >> 7, 8, e & 127, c);
                *reinterpret_cast<uint16_t*>(g_mts + off)        = b2s(hb);
                *reinterpret_cast<uint16_t*>(g_mts + (off ^ 64)) = b2s(lb);
            }
    } else {
        int c = tid;
        float acc = 0.0f;
        for (int d = 0; d < 256; ++d) acc += Wk[(long)d * 256 + c] * bq[d];
        g_beta[c] = acc;
    }
}

// x conv (0..4095) + w vector (4096..6143)
__global__ void __launch_bounds__(NTHREADS) xconv_kernel(const float* __restrict__ src)
{
    int bid = blockIdx.x, tid = threadIdx.x;
    if (bid < 4096) {
        long i = (long)bid * NTHREADS + tid;
        float4 v = reinterpret_cast<const float4*>(src)[i];
        long e = i * 4;
        int r = (int)(e >> 8), k = (int)(e & 255);
        size_t off = sbf_off(r >> 7, 8, r & 127, k);
        __half2 h0, l0, h1, l1;
        split2h(v.x, v.y, h0, l0);
        split2h(v.z, v.w, h1, l1);
        *reinterpret_cast<uint2*>(g_xs + off)        = make_uint2(b2u(h0), b2u(h1));
        *reinterpret_cast<uint2*>(g_xs + (off ^ 64)) = make_uint2(b2u(l0), b2u(l1));
    } else {
        int row = (bid - 4096) * 8 + (tid >> 5);
        int lane = tid & 31;
        float p = 0.0f;
#pragma unroll
        for (int e = 0; e < 8; ++e)
            p += src[(long)row * 256 + lane + e * 32] * g_beta[lane + e * 32];
#pragma unroll
        for (int o = 16; o; o >>= 1) p += __shfl_xor_sync(0xffffffffu, p, o);
        if (!lane) g_w[row] = p;
    }
}

// ---------------------------------------------------------------------------
// Stage 1: proj (fp16 3-term). grid (2, 128, 2): sel0 qm, sel1 v (single fp16).
// ---------------------------------------------------------------------------
__global__ void __launch_bounds__(NTHREADS, 2)
proj_kernel(const float* __restrict__ bv)
{
    extern __shared__ char smem[];
    int n0 = blockIdx.x * 128; long m0 = (long)blockIdx.y * 128; int sel = blockIdx.z;
    const char* B = (sel == 0)
        ? g_mts + (size_t)(n0 >> 7) * 8 * SLAB_F
        : g_wvs + (size_t)(n0 >> 7) * 8 * SLAB_F;
    float acc[4][4][4] = {};
    gemm_bulk<8, 1, NSTG_F>(g_xs + (m0 >> 7) * 8 * SLAB_F, B, smem, acc);
    if (sel == 0) {
        char* dst = g_qms + ((size_t)(m0 >> 7) * 8 + (n0 >> 5)) * SLAB_F;
        epi_split_h(acc, smem, dst, g_zero + n0);
    } else {
        int b = (int)(m0 >> 10), tok0 = (int)(m0 & 1023);
        char* dst = g_vts + ((size_t)(b * 2 + (n0 >> 7)) * 32 + (tok0 >> 5)) * SLAB_H;
        epi_t_h16(acc, smem, dst, bv + n0);
    }
}

// ---------------------------------------------------------------------------
// Stage 2: attn_norm = exp(qm x^T + w_j)/zp_tile, fp16 3-term. grid (8, 8, 16)
// ---------------------------------------------------------------------------
__global__ void __launch_bounds__(NTHREADS, 2) scores_kernel()
{
    extern __shared__ char smem[];
    int n0 = blockIdx.x * 128, m0 = blockIdx.y * 128, b = blockIdx.z;
    float acc[4][4][4] = {};
    gemm_bulk<8, 1, NSTG_F>(g_qms + (size_t)((b * NTOK + m0) >> 7) * 8 * SLAB_F,
                            g_xs  + (size_t)((b * NTOK + n0) >> 7) * 8 * SLAB_F,
                            smem, acc);
    char* dst = g_attns + ((size_t)((b * NTOK + m0) >> 7) * 32 + (n0 >> 5)) * SLAB_H;
    epi_attn(acc, smem, dst, g_w + (long)b * NTOK + n0,
             g_zp + ((long)b * 8 + blockIdx.x) * NTOK + m0);
}

// ---------------------------------------------------------------------------
// Stage 3: o^T, fp16 1-term with per-tile A rescale. grid (2, 8, 16)
// ---------------------------------------------------------------------------
__global__ void __launch_bounds__(NTHREADS, 2) av_kernel()
{
    extern __shared__ char smem[];
    int c0 = blockIdx.x * 128, tok0 = blockIdx.y * 128, b = blockIdx.z;
    __half* ss = reinterpret_cast<__half*>(smem + NSTG_H * 2 * SLAB_H + 64);
    if (threadIdx.x < 128) {
        float z[8], Z = 0.0f;
#pragma unroll
        for (int t = 0; t < 8; ++t) {
            z[t] = g_zp[((long)b * 8 + t) * NTOK + tok0 + threadIdx.x];
            Z += z[t];
        }
        float invZ = 1.0f / Z;
#pragma unroll
        for (int t = 0; t < 8; ++t)
            ss[t * 128 + threadIdx.x] = __float2half(z[t] * invZ);
    }
    float acc[4][4][4] = {};
    gemm_bulk<32, 3, NSTG_H>(g_attns + (size_t)((b * NTOK + tok0) >> 7) * 32 * SLAB_H,
                             g_vts   + (size_t)(b * 2 + (c0 >> 7))      * 32 * SLAB_H,
                             smem, acc, ss);
    char* dst = g_ots + ((size_t)(b * 2 + (c0 >> 7)) * 32 + (tok0 >> 5)) * SLAB_H;
    epi_t_h16(acc, smem, dst, nullptr);
}

// ---------------------------------------------------------------------------
// Stage 4: z = Wp^T o, fp16 1-term. grid (2, 8, 16)
// ---------------------------------------------------------------------------
__global__ void __launch_bounds__(NTHREADS, 2) final_kernel(float* __restrict__ z)
{
    extern __shared__ char smem[];
    int c0 = blockIdx.x * 128, p0 = blockIdx.y * 128, b = blockIdx.z;
    float acc[4][4][4] = {};
    gemm_bulk<32, 3, NSTG_H>(g_wpts + (size_t)(p0 >> 7) * 32 * SLAB_H,
                             g_ots  + (size_t)(b * 2 + (c0 >> 7)) * 32 * SLAB_H,
                             smem, acc);
    epi_f32(acc, z + ((long)b * NTOK + p0) * CDIM + c0, CDIM);
}

// ---------------------------------------------------------------------------
extern "C" void kernel_launch(void* const* d_in, const int* in_sizes, int n_in,
                              void* d_out, int out_size)
{
    const float* x  = (const float*)d_in[0];
    const float* Wq = (const float*)d_in[1];
    const float* bq = (const float*)d_in[2];
    const float* Wk = (const float*)d_in[3];
    const float* Wv = (const float*)d_in[5];
    const float* bv = (const float*)d_in[6];
    const float* Wp = (const float*)d_in[7];
    float* out = (float*)d_out;

    cudaFuncSetAttribute(proj_kernel,   cudaFuncAttributeMaxDynamicSharedMemorySize, SMEM_3T);
    cudaFuncSetAttribute(scores_kernel, cudaFuncAttributeMaxDynamicSharedMemorySize, SMEM_3T);
    cudaFuncSetAttribute(av_kernel,     cudaFuncAttributeMaxDynamicSharedMemorySize, SMEM_AV);
    cudaFuncSetAttribute(final_kernel,  cudaFuncAttributeMaxDynamicSharedMemorySize, SMEM_1T);

    prep_kernel <<<dim3(1105), NTHREADS>>>(Wq, Wk, Wv, Wp, bq);            // 1
    xconv_kernel<<<dim3(6144), NTHREADS>>>(x);                             // 2
    proj_kernel  <<<dim3(2, 128, 2), NTHREADS, SMEM_3T>>>(bv);             // 3
    scores_kernel<<<dim3(8, 8, 16),  NTHREADS, SMEM_3T>>>();               // 4 <- profiled
    av_kernel    <<<dim3(2, 8, 16),  NTHREADS, SMEM_AV>>>();               // 5
    final_kernel <<<dim3(2, 8, 16),  NTHREADS, SMEM_1T>>>(out);            // 6
}

// round 16
// speedup vs baseline: 1.1621x; 1.0831x over previous
#include <cuda_runtime.h>
#include <cuda_bf16.h>
#include <cuda_fp16.h>
#include <cstdint>

#define BATCH 16
#define NTOK  1024
#define CDIM  256
#define NTHREADS 256
#define NSTG_F 3                        // stages for split (32KB) kernels
#define NSTG_H 4                        // stages for 1-term h16 (16KB) kernels
#define SLAB_F 16384                    // split slab: 128 rows x 128B
#define SLAB_H 8192                     // single-fp16 slab: 128 rows x 64B
#define SMEM_3T (NSTG_F*2*SLAB_F + 4096)   // ring 96KB + mbar (zsm overlays ring)
#define SMEM_AV (NSTG_H*2*SLAB_H + 4096)   // ring 64KB + mbar + ss
#define SMEM_1T (NSTG_H*2*SLAB_H + 1024)

// ---------------------------------------------------------------------------
// Split tiled format: rows in tiles of 128; tile t, k-slab s (32 k) is a
// contiguous 16KB smem image: row r at r*128, chunk cc at (cc^(r&7))*16;
// chunks 0-3 hi, 4-7 lo (addr = hi ^ 64). fp16 pairs.
// Single-fp16 format: 8KB slabs, row r at r*64, chunk cc at (cc^((r>>1)&3))*16.
// ---------------------------------------------------------------------------
__device__ __align__(128) char g_xs  [16384*1024];      // x    fp16 split
__device__ __align__(128) char g_wvs [256*1024];        // Wv   fp16 split
__device__ __align__(128) char g_mts [256*1024];        // Mt = (Wq^T Wk)^T [e][c], fp16 split
__device__ __align__(128) char g_qms [16384*1024];      // qm = x·M, fp16 split
__device__ __align__(128) char g_vts [16*256*2048];     // v^T  fp16 single
__device__ __align__(128) char g_ots [16*256*2048];     // o^T  fp16 single
__device__ __align__(128) char g_attns[(size_t)16384*2048]; // attn_norm fp16 single
__device__ __align__(128) char g_wpts[1024*2048];       // Wp^T fp16 single
__device__ float g_zp[BATCH*8*NTOK];                    // per (b, n-tile, tok) exp sums
__device__ float g_w[BATCH*NTOK];                       // w_j = x_j . (Wk^T bq)
__device__ float g_beta[256];
__device__ float g_zero[256];

// ---------------------------------------------------------------------------
__device__ __forceinline__ uint32_t smem_u32(const void* p){
    uint32_t a;
    asm("{ .reg .u64 t; cvta.to.shared.u64 t, %1; cvt.u32.u64 %0, t; }" : "=r"(a) : "l"(p));
    return a;
}
__device__ __forceinline__ void ldsm4(uint32_t* r, uint32_t addr){
    asm volatile("ldmatrix.sync.aligned.m8n8.x4.shared.b16 {%0,%1,%2,%3}, [%4];"
        : "=r"(r[0]), "=r"(r[1]), "=r"(r[2]), "=r"(r[3]) : "r"(addr));
}
__device__ __forceinline__ void mma_f16(float* d, const uint32_t* a, const uint32_t* b){
    asm volatile("mma.sync.aligned.m16n8k16.row.col.f32.f16.f16.f32 "
        "{%0,%1,%2,%3}, {%4,%5,%6,%7}, {%8,%9}, {%0,%1,%2,%3};"
        : "+f"(d[0]), "+f"(d[1]), "+f"(d[2]), "+f"(d[3])
        : "r"(a[0]), "r"(a[1]), "r"(a[2]), "r"(a[3]), "r"(b[0]), "r"(b[1]));
}
__device__ __forceinline__ void split2h(float v0, float v1, __half2& h, __half2& l){
    h = __floats2half2_rn(v0, v1);
    l = __floats2half2_rn(v0 - __half2float(__low2half(h)),
                          v1 - __half2float(__high2half(h)));
}
template<class T> __device__ __forceinline__ uint32_t b2u(T v){
    uint32_t u; memcpy(&u, &v, 4); return u;
}
template<class T> __device__ __forceinline__ uint16_t b2s(T v){
    uint16_t u; memcpy(&u, &v, 2); return u;
}
__device__ __forceinline__ uint32_t h2mul(uint32_t a, uint32_t s){
    __half2 x, y; memcpy(&x, &a, 4); memcpy(&y, &s, 4);
    __half2 r = __hmul2(x, y); uint32_t u; memcpy(&u, &r, 4); return u;
}

// global tiled-format offsets (producers)
__device__ __forceinline__ size_t sbf_off(long tile, int nslab, int r, int k){
    int cc = (k & 31) >> 3;
    return ((size_t)(tile * nslab + (k >> 5)) << 14)
         + (size_t)(r * 128) + (size_t)(((cc ^ (r & 7)) << 4) + (k & 7) * 2);
}
__device__ __forceinline__ size_t h16_off(long tile, int nslab, int r, int k){
    int cc = (k & 31) >> 3;
    return ((size_t)(tile * nslab + (k >> 5)) << 13)
         + (size_t)(r * 64) + (size_t)(((cc ^ ((r >> 1) & 3)) << 4) + (k & 7) * 2);
}
// local (within stage region) offsets
__device__ __forceinline__ int loc_f(int r, int k){
    int cc = (k & 31) >> 3;
    return ((k >> 5) << 14) + r * 128 + ((cc ^ (r & 7)) << 4) + (k & 7) * 2;
}
__device__ __forceinline__ int loc_h(int r, int k){
    int cc = (k & 31) >> 3;
    return ((k >> 5) << 13) + r * 64 + ((cc ^ ((r >> 1) & 3)) << 4) + (k & 7) * 2;
}

#define MBAR_INIT(mb,c)  asm volatile("mbarrier.init.shared.b64 [%0], %1;" :: "r"(mb), "r"((uint32_t)(c)) : "memory")
#define MBAR_EXPECT(mb,n) asm volatile("mbarrier.arrive.expect_tx.shared.b64 _, [%0], %1;" :: "r"(mb), "r"((uint32_t)(n)) : "memory")
#define BULK_G2S(dst,src,n,mb) asm volatile("cp.async.bulk.shared::cta.global.mbarrier::complete_tx::bytes [%0], [%1], %2, [%3];" :: "r"(dst), "l"(src), "r"((uint32_t)(n)), "r"(mb) : "memory")
#define BULK_S2G(dst,src,n) asm volatile("cp.async.bulk.global.shared::cta.bulk_group [%0], [%1], %2;" :: "l"(dst), "r"(src), "r"((uint32_t)(n)) : "memory")
#define BULK_COMMIT() asm volatile("cp.async.bulk.commit_group;" ::: "memory")
#define BULK_WAIT0()  asm volatile("cp.async.bulk.wait_group 0;" ::: "memory")
#define FENCE_ASYNC() asm volatile("fence.proxy.async.shared::cta;" ::: "memory")

#define MBAR_WAIT(mb, par) do { \
    uint32_t _m = (uint32_t)(mb), _p = (uint32_t)(par), _d; \
    asm volatile("{\n\t.reg .pred p;\n\t" \
        "mbarrier.try_wait.parity.acquire.cta.shared::cta.b64 p, [%1], %2;\n\t" \
        "selp.b32 %0, 1, 0, p;\n\t}" : "=r"(_d) : "r"(_m), "r"(_p) : "memory"); \
    if (!_d) { \
        asm volatile("{\n\t.reg .pred P1;\n\t" \
            "WL_%=:\n\t" \
            "mbarrier.try_wait.parity.acquire.cta.shared::cta.b64 P1, [%0], %1, 0x989680;\n\t" \
            "@P1 bra.uni WD_%=;\n\t" \
            "bra.uni WL_%=;\n\t" \
            "WD_%=:\n\t}" :: "r"(_m), "r"(_p) : "memory"); \
    } \
} while(0)

// ---------------------------------------------------------------------------
// 3-term fp16 compute (split A, split B). CTA 128x128, warps 2(M)x4(N).
// ---------------------------------------------------------------------------
__device__ __forceinline__ void compute_slab3(char* buf, float acc[4][4][4])
{
    int tid = threadIdx.x, lane = tid & 31, wid = tid >> 5;
    uint32_t sA = smem_u32(buf), sB = sA + SLAB_F;
    int mw = (wid & 1) * 64, nw = (wid >> 1) * 32;
    int arow = lane & 15, ahalf = lane >> 4;
    int brow = (lane & 7) + ((lane >> 4) & 1) * 8, bhalf = (lane >> 3) & 1;

#pragma unroll
    for (int ks = 0; ks < 2; ++ks) {
        uint32_t bh[8], bl[8];
#pragma unroll
        for (int nj = 0; nj < 2; ++nj) {
            int r = nw + nj * 16 + brow;
            int c = ks * 2 + bhalf;
            ldsm4(bh + nj * 4, sB + r * 128 + (((c    ) ^ (r & 7)) << 4));
            ldsm4(bl + nj * 4, sB + r * 128 + (((c + 4) ^ (r & 7)) << 4));
        }
#pragma unroll
        for (int mi = 0; mi < 4; ++mi) {
            int r = mw + mi * 16 + arow;
            int c = ks * 2 + ahalf;
            uint32_t ah[4], al[4];
            ldsm4(ah, sA + r * 128 + (((c    ) ^ (r & 7)) << 4));
            ldsm4(al, sA + r * 128 + (((c + 4) ^ (r & 7)) << 4));
#pragma unroll
            for (int j = 0; j < 4; ++j) {
                const uint32_t* bhf = &bh[(j >> 1) * 4 + (j & 1) * 2];
                const uint32_t* blf = &bl[(j >> 1) * 4 + (j & 1) * 2];
                float* d = acc[mi][j];
                mma_f16(d, ah, bhf);
                mma_f16(d, al, bhf);
                mma_f16(d, ah, blf);
            }
        }
    }
}

// ---------------------------------------------------------------------------
// 1-term fp16 on SPLIT layout (reads hi chunks only; lo bytes ignored).
// ---------------------------------------------------------------------------
__device__ __forceinline__ void compute_slab1f(char* buf, float acc[4][4][4])
{
    int tid = threadIdx.x, lane = tid & 31, wid = tid >> 5;
    uint32_t sA = smem_u32(buf), sB = sA + SLAB_F;
    int mw = (wid & 1) * 64, nw = (wid >> 1) * 32;
    int arow = lane & 15, ahalf = lane >> 4;
    int brow = (lane & 7) + ((lane >> 4) & 1) * 8, bhalf = (lane >> 3) & 1;

#pragma unroll
    for (int ks = 0; ks < 2; ++ks) {
        uint32_t bh[8];
#pragma unroll
        for (int nj = 0; nj < 2; ++nj) {
            int r = nw + nj * 16 + brow;
            int c = ks * 2 + bhalf;
            ldsm4(bh + nj * 4, sB + r * 128 + ((c ^ (r & 7)) << 4));
        }
#pragma unroll
        for (int mi = 0; mi < 4; ++mi) {
            int r = mw + mi * 16 + arow;
            int c = ks * 2 + ahalf;
            uint32_t ah[4];
            ldsm4(ah, sA + r * 128 + ((c ^ (r & 7)) << 4));
#pragma unroll
            for (int j = 0; j < 4; ++j)
                mma_f16(acc[mi][j], ah, &bh[(j >> 1) * 4 + (j & 1) * 2]);
        }
    }
}

// ---------------------------------------------------------------------------
// 1-term fp16 compute (single A, single B; 64B rows). Optional A-frag scale.
// ---------------------------------------------------------------------------
template<bool SCALE>
__device__ __forceinline__ void compute_slab1(char* buf, float acc[4][4][4],
        const __half* __restrict__ ss)
{
    int tid = threadIdx.x, lane = tid & 31, wid = tid >> 5;
    uint32_t sA = smem_u32(buf), sB = sA + SLAB_H;
    int mw = (wid & 1) * 64, nw = (wid >> 1) * 32;
    int arow = lane & 15, ahalf = lane >> 4;
    int brow = (lane & 7) + ((lane >> 4) & 1) * 8, bhalf = (lane >> 3) & 1;
    int r0 = lane >> 2;

    uint32_t sv0[4], sv1[4];
    if (SCALE) {
#pragma unroll
        for (int mi = 0; mi < 4; ++mi) {
            int rr = mw + mi * 16 + r0;
            sv0[mi] = b2u(__half2half2(ss[rr]));
            sv1[mi] = b2u(__half2half2(ss[rr + 8]));
        }
    }

#pragma unroll
    for (int ks = 0; ks < 2; ++ks) {
        uint32_t bh[8];
#pragma unroll
        for (int nj = 0; nj < 2; ++nj) {
            int r = nw + nj * 16 + brow;
            int c = ks * 2 + bhalf;
            ldsm4(bh + nj * 4, sB + r * 64 + ((c ^ ((r >> 1) & 3)) << 4));
        }
#pragma unroll
        for (int mi = 0; mi < 4; ++mi) {
            int r = mw + mi * 16 + arow;
            int c = ks * 2 + ahalf;
            uint32_t ah[4];
            ldsm4(ah, sA + r * 64 + ((c ^ ((r >> 1) & 3)) << 4));
            if (SCALE) {
                ah[0] = h2mul(ah[0], sv0[mi]);
                ah[2] = h2mul(ah[2], sv0[mi]);
                ah[1] = h2mul(ah[1], sv1[mi]);
                ah[3] = h2mul(ah[3], sv1[mi]);
            }
#pragma unroll
            for (int j = 0; j < 4; ++j)
                mma_f16(acc[mi][j], ah, &bh[(j >> 1) * 4 + (j & 1) * 2]);
        }
    }
}

// ---------------------------------------------------------------------------
// Bulk-copy mainloop. MODE 1: 3-term split; MODE 2: 1-term split; MODE 3: 1-term h16.
// ---------------------------------------------------------------------------
template<int NC, int MODE, int NST>
__device__ __forceinline__ void gemm_bulk(const char* __restrict__ A,
                                          const char* __restrict__ B,
                                          char* smem, float acc[4][4][4],
                                          const __half* __restrict__ ss = nullptr)
{
    constexpr int SL  = (MODE == 3) ? SLAB_H : SLAB_F;
    constexpr int STG = 2 * SL;
    uint32_t mb = smem_u32(smem + NST * STG);
    int tid = threadIdx.x;
    if (tid == 0) {
#pragma unroll
        for (int s = 0; s < NST; ++s) MBAR_INIT(mb + 8 * s, 1);
        FENCE_ASYNC();
    }
    __syncthreads();
    if (tid == 0) {
#pragma unroll
        for (int s = 0; s < NST - 1; ++s) {
            uint32_t m = mb + 8 * s;
            uint32_t d = smem_u32(smem + s * STG);
            MBAR_EXPECT(m, STG);
            BULK_G2S(d,      A + (size_t)s * SL, SL, m);
            BULK_G2S(d + SL, B + (size_t)s * SL, SL, m);
        }
    }
#pragma unroll 4
    for (int c = 0; c < NC; ++c) {
        int s = c % NST;
        MBAR_WAIT(mb + 8 * s, (c / NST) & 1);
        __syncthreads();
        int nc = c + NST - 1;
        if (tid == 0 && nc < NC) {
            int sn = nc % NST;
            uint32_t m = mb + 8 * sn;
            uint32_t d = smem_u32(smem + sn * STG);
            MBAR_EXPECT(m, STG);
            BULK_G2S(d,      A + (size_t)nc * SL, SL, m);
            BULK_G2S(d + SL, B + (size_t)nc * SL, SL, m);
        }
        if (MODE == 3) {
            if (ss) compute_slab1<true >(smem + s * STG, acc, ss + (c >> 2) * 128);
            else    compute_slab1<false>(smem + s * STG, acc, nullptr);
        } else if (MODE == 2) {
            compute_slab1f(smem + s * STG, acc);
        } else {
            compute_slab3(smem + s * STG, acc);
        }
    }
}

// drain a staged 4-slab region to global
template<int SL>
__device__ __forceinline__ void stage_drain(char* smem, char* dst)
{
    __syncthreads();
    if (threadIdx.x == 0) {
        FENCE_ASYNC();
#pragma unroll
        for (int sl = 0; sl < 4; ++sl)
            BULK_S2G(dst + sl * SL, smem_u32(smem + sl * SL), SL);
        BULK_COMMIT();
        BULK_WAIT0();
    }
}

// ---------------------------------------------------------------------------
// Epilogues. Frag: d0,d1 -> (row=lane>>2, col=(lane&3)*2+e), d2,d3 row+8.
// ---------------------------------------------------------------------------
__device__ __forceinline__ void epi_f32(const float acc[4][4][4],
        float* __restrict__ Cg, int ldc)
{
    int tid = threadIdx.x, lane = tid & 31, wid = tid >> 5;
    int row0 = (wid & 1) * 64 + (lane >> 2), col0 = (wid >> 1) * 32 + (lane & 3) * 2;
#pragma unroll
    for (int mi = 0; mi < 4; ++mi)
#pragma unroll
        for (int j = 0; j < 4; ++j) {
            int c = col0 + j * 8;
#pragma unroll
            for (int h = 0; h < 2; ++h) {
                int r = row0 + mi * 16 + h * 8;
                *reinterpret_cast<float2*>(Cg + (long)r * ldc + c) =
                    make_float2(acc[mi][j][h * 2], acc[mi][j][h * 2 + 1]);
            }
        }
}

// qm: fp16 split normal; 64KB stage at smem base.
__device__ __forceinline__ void epi_split_h(const float acc[4][4][4],
        char* smem, char* dst, const float* __restrict__ bias)
{
    int tid = threadIdx.x, lane = tid & 31, wid = tid >> 5;
    int rw0 = (wid & 1) * 64 + (lane >> 2), cw0 = (wid >> 1) * 32 + (lane & 3) * 2;
    __syncthreads();
#pragma unroll
    for (int mi = 0; mi < 4; ++mi)
#pragma unroll
        for (int j = 0; j < 4; ++j) {
            int c = cw0 + j * 8;
            float b0 = bias[c], b1 = bias[c + 1];
#pragma unroll
            for (int h = 0; h < 2; ++h) {
                int r = rw0 + mi * 16 + h * 8;
                __half2 hh, ll;
                split2h(acc[mi][j][h * 2] + b0, acc[mi][j][h * 2 + 1] + b1, hh, ll);
                int off = loc_f(r, c);
                *reinterpret_cast<uint32_t*>(smem + off)        = b2u(hh);
                *reinterpret_cast<uint32_t*>(smem + (off ^ 64)) = b2u(ll);
            }
        }
    stage_drain<SLAB_F>(smem, dst);
}

// transposed single-fp16 (v^T with bias, o^T without); 32KB stage.
__device__ __forceinline__ void epi_t_h16(const float acc[4][4][4],
        char* smem, char* dst, const float* __restrict__ bias)
{
    int tid = threadIdx.x, lane = tid & 31, wid = tid >> 5;
    int rw0 = (wid & 1) * 64 + (lane >> 2), cw0 = (wid >> 1) * 32 + (lane & 3) * 2;
    __syncthreads();
#pragma unroll
    for (int mi = 0; mi < 4; ++mi)
#pragma unroll
        for (int j = 0; j < 4; ++j)
#pragma unroll
            for (int h = 0; h < 2; ++h) {
                int m = rw0 + mi * 16 + h * 8;
#pragma unroll
                for (int e = 0; e < 2; ++e) {
                    int n = cw0 + j * 8 + e;
                    float v = acc[mi][j][h * 2 + e] + (bias ? bias[n] : 0.0f);
                    *reinterpret_cast<uint16_t*>(smem + loc_h(n, m)) = b2s(__float2half(v));
                }
            }
    stage_drain<SLAB_H>(smem, dst);
}

// attn: exp(acc + w_col), per-tile normalize, single fp16 + partial sums.
// Stage 32KB at smem base; zsm overlays ring at +32KB (ring is drained here).
__device__ __forceinline__ void epi_attn(const float acc[4][4][4], char* smem,
        char* dst, const float* __restrict__ wcol, float* __restrict__ zp_out)
{
    int tid = threadIdx.x, lane = tid & 31, wid = tid >> 5;
    int rw0 = (wid & 1) * 64 + (lane >> 2), cw0 = (wid >> 1) * 32 + (lane & 3) * 2;
    float* zsm = reinterpret_cast<float*>(smem + 4 * SLAB_H);
    __syncthreads();

    float wc[8];
#pragma unroll
    for (int j = 0; j < 4; ++j) {
        wc[j * 2]     = wcol[cw0 + j * 8];
        wc[j * 2 + 1] = wcol[cw0 + j * 8 + 1];
    }

    float ex[4][4][4];
#pragma unroll
    for (int mi = 0; mi < 4; ++mi) {
#pragma unroll
        for (int h = 0; h < 2; ++h) {
            int r = rw0 + mi * 16 + h * 8;
            float rs = 0.0f;
#pragma unroll
            for (int j = 0; j < 4; ++j) {
                float e0 = __expf(acc[mi][j][h * 2]     + wc[j * 2]);
                float e1 = __expf(acc[mi][j][h * 2 + 1] + wc[j * 2 + 1]);
                ex[mi][j][h * 2] = e0; ex[mi][j][h * 2 + 1] = e1;
                rs += e0 + e1;
            }
            rs += __shfl_xor_sync(0xffffffffu, rs, 1);
            rs += __shfl_xor_sync(0xffffffffu, rs, 2);
            if ((lane & 3) == 0)
                zsm[(wid >> 1) * 128 + r] = rs;
        }
    }
    __syncthreads();
    if (tid < 128)
        zp_out[tid] = zsm[tid] + zsm[128 + tid] + zsm[256 + tid] + zsm[384 + tid];
#pragma unroll
    for (int mi = 0; mi < 4; ++mi)
#pragma unroll
        for (int h = 0; h < 2; ++h) {
            int r = rw0 + mi * 16 + h * 8;
            float inv = 1.0f / (zsm[r] + zsm[128 + r] + zsm[256 + r] + zsm[384 + r]);
#pragma unroll
            for (int j = 0; j < 4; ++j) {
                int c = cw0 + j * 8;
                __half2 hv = __floats2half2_rn(ex[mi][j][h * 2] * inv,
                                               ex[mi][j][h * 2 + 1] * inv);
                *reinterpret_cast<uint32_t*>(smem + loc_h(r, c)) = b2u(hv);
            }
        }
    stage_drain<SLAB_H>(smem, dst);
}

// ---------------------------------------------------------------------------
// Prep+xconv fused: Wv (0..63) | Wp^T (64..1087) | Mt (1088..1103) |
//                   beta (1104) | x conv (1105..5200)
// ---------------------------------------------------------------------------
__global__ void __launch_bounds__(NTHREADS) prepx_kernel(
        const float* __restrict__ Wq, const float* __restrict__ Wk,
        const float* __restrict__ Wv, const float* __restrict__ Wp,
        const float* __restrict__ bq, const float* __restrict__ x)
{
    int bid = blockIdx.x, tid = threadIdx.x;
    if (bid < 64) {
        long i = (long)bid * NTHREADS + tid;
        float4 v = reinterpret_cast<const float4*>(Wv)[i];
        long e = i * 4;
        int r = (int)(e >> 8), k = (int)(e & 255);
        size_t off = sbf_off(r >> 7, 8, r & 127, k);
        __half2 h0, l0, h1, l1;
        split2h(v.x, v.y, h0, l0);
        split2h(v.z, v.w, h1, l1);
        *reinterpret_cast<uint2*>(g_wvs + off)        = make_uint2(b2u(h0), b2u(h1));
        *reinterpret_cast<uint2*>(g_wvs + (off ^ 64)) = make_uint2(b2u(l0), b2u(l1));
    } else if (bid < 1088) {
        __shared__ float t[32][33];
        int b2 = bid - 64;
        int h = b2 >> 5, n0 = (b2 & 31) * 32;
        int tx = tid & 31, ty = tid >> 5;
        const float* src = Wp + (long)h * 32768 + (long)n0 * 32;
#pragma unroll
        for (int i = 0; i < 4; ++i) t[ty + i * 8][tx] = src[(ty + i * 8) * 32 + tx];
        __syncthreads();
#pragma unroll
        for (int i = 0; i < 4; ++i) {
            int w = ty + i * 8;
            int p = h * 32 + w, n = n0 + tx;
            *reinterpret_cast<uint16_t*>(g_wpts + h16_off(p >> 7, 32, p & 127, n)) =
                b2s(__float2half(t[tx][w]));
        }
    } else if (bid < 1104) {
        __shared__ float As[32][64], Bs[32][64];
        int mt = bid - 1088;
        int e0 = (mt >> 2) * 64, c0 = (mt & 3) * 64;
        int tx = tid & 15, ty = tid >> 4;
        float acc[4][4] = {};
        for (int k0 = 0; k0 < 256; k0 += 32) {
            for (int i = tid; i < 2048; i += NTHREADS) {
                int dd = i >> 6, ee = i & 63;
                As[dd][ee] = Wk[(long)(k0 + dd) * 256 + e0 + ee];
                Bs[dd][ee] = Wq[(long)(k0 + dd) * 256 + c0 + ee];
            }
            __syncthreads();
#pragma unroll 8
            for (int dd = 0; dd < 32; ++dd) {
                float a[4], b[4];
#pragma unroll
                for (int i = 0; i < 4; ++i) { a[i] = As[dd][ty * 4 + i]; b[i] = Bs[dd][tx * 4 + i]; }
#pragma unroll
                for (int i = 0; i < 4; ++i)
#pragma unroll
                    for (int j = 0; j < 4; ++j) acc[i][j] += a[i] * b[j];
            }
            __syncthreads();
        }
#pragma unroll
        for (int i = 0; i < 4; ++i)
#pragma unroll
            for (int j = 0; j < 4; ++j) {
                int e = e0 + ty * 4 + i, c = c0 + tx * 4 + j;
                __half hb = __float2half(acc[i][j]);
                __half lb = __float2half(acc[i][j] - __half2float(hb));
                size_t off = sbf_off(e >> 7, 8, e & 127, c);
                *reinterpret_cast<uint16_t*>(g_mts + off)        = b2s(hb);
                *reinterpret_cast<uint16_t*>(g_mts + (off ^ 64)) = b2s(lb);
            }
    } else if (bid == 1104) {
        int c = tid;
        float acc = 0.0f;
        for (int d = 0; d < 256; ++d) acc += Wk[(long)d * 256 + c] * bq[d];
        g_beta[c] = acc;
    } else {
        long i = (long)(bid - 1105) * NTHREADS + tid;
        float4 v = reinterpret_cast<const float4*>(x)[i];
        long e = i * 4;
        int r = (int)(e >> 8), k = (int)(e & 255);
        size_t off = sbf_off(r >> 7, 8, r & 127, k);
        __half2 h0, l0, h1, l1;
        split2h(v.x, v.y, h0, l0);
        split2h(v.z, v.w, h1, l1);
        *reinterpret_cast<uint2*>(g_xs + off)        = make_uint2(b2u(h0), b2u(h1));
        *reinterpret_cast<uint2*>(g_xs + (off ^ 64)) = make_uint2(b2u(l0), b2u(l1));
    }
}

// ---------------------------------------------------------------------------
// Stage 1: proj. grid (2, 128, 3): sel0 qm (3-term), sel1 v (1-term split),
// sel2 w-vector (blockIdx.x==0 only; reads x fp32 + g_beta).
// ---------------------------------------------------------------------------
__global__ void __launch_bounds__(NTHREADS, 2)
proj_kernel(const float* __restrict__ bv, const float* __restrict__ x)
{
    extern __shared__ char smem[];
    int n0 = blockIdx.x * 128; long m0 = (long)blockIdx.y * 128; int sel = blockIdx.z;
    if (sel == 2) {
        if (blockIdx.x != 0) return;
        // w[m0 + r] for r in 0..127; warp per 4 rows x 8 iters
        int lane = threadIdx.x & 31, wrp = threadIdx.x >> 5;
        float beta = g_beta[lane] , beta2 = 0.0f;   // lanes cover 32 cols per pass
#pragma unroll
        for (int rr = wrp; rr < 128; rr += 8) {
            const float* row = x + (m0 + rr) * 256;
            float p = 0.0f;
#pragma unroll
            for (int e = 0; e < 8; ++e)
                p += row[lane + e * 32] * g_beta[lane + e * 32];
#pragma unroll
            for (int o = 16; o; o >>= 1) p += __shfl_xor_sync(0xffffffffu, p, o);
            if (!lane) g_w[m0 + rr] = p;
        }
        (void)beta; (void)beta2;
        return;
    }
    float acc[4][4][4] = {};
    if (sel == 0) {
        gemm_bulk<8, 1, NSTG_F>(g_xs + (m0 >> 7) * 8 * SLAB_F,
                                g_mts + (size_t)(n0 >> 7) * 8 * SLAB_F, smem, acc);
        char* dst = g_qms + ((size_t)(m0 >> 7) * 8 + (n0 >> 5)) * SLAB_F;
        epi_split_h(acc, smem, dst, g_zero + n0);
    } else {
        gemm_bulk<8, 2, NSTG_F>(g_xs + (m0 >> 7) * 8 * SLAB_F,
                                g_wvs + (size_t)(n0 >> 7) * 8 * SLAB_F, smem, acc);
        int b = (int)(m0 >> 10), tok0 = (int)(m0 & 1023);
        char* dst = g_vts + ((size_t)(b * 2 + (n0 >> 7)) * 32 + (tok0 >> 5)) * SLAB_H;
        epi_t_h16(acc, smem, dst, bv + n0);
    }
}

// ---------------------------------------------------------------------------
// Stage 2: attn_norm = exp(qm x^T + w_j)/zp_tile, fp16 3-term. grid (8, 8, 16)
// ---------------------------------------------------------------------------
__global__ void __launch_bounds__(NTHREADS, 2) scores_kernel()
{
    extern __shared__ char smem[];
    int n0 = blockIdx.x * 128, m0 = blockIdx.y * 128, b = blockIdx.z;
    float acc[4][4][4] = {};
    gemm_bulk<8, 1, NSTG_F>(g_qms + (size_t)((b * NTOK + m0) >> 7) * 8 * SLAB_F,
                            g_xs  + (size_t)((b * NTOK + n0) >> 7) * 8 * SLAB_F,
                            smem, acc);
    char* dst = g_attns + ((size_t)((b * NTOK + m0) >> 7) * 32 + (n0 >> 5)) * SLAB_H;
    epi_attn(acc, smem, dst, g_w + (long)b * NTOK + n0,
             g_zp + ((long)b * 8 + blockIdx.x) * NTOK + m0);
}

// ---------------------------------------------------------------------------
// Stage 3: o^T, fp16 1-term with per-tile A rescale. grid (2, 8, 16)
// ---------------------------------------------------------------------------
__global__ void __launch_bounds__(NTHREADS, 2) av_kernel()
{
    extern __shared__ char smem[];
    int c0 = blockIdx.x * 128, tok0 = blockIdx.y * 128, b = blockIdx.z;
    __half* ss = reinterpret_cast<__half*>(smem + NSTG_H * 2 * SLAB_H + 64);
    if (threadIdx.x < 128) {
        float z[8], Z = 0.0f;
#pragma unroll
        for (int t = 0; t < 8; ++t) {
            z[t] = g_zp[((long)b * 8 + t) * NTOK + tok0 + threadIdx.x];
            Z += z[t];
        }
        float invZ = 1.0f / Z;
#pragma unroll
        for (int t = 0; t < 8; ++t)
            ss[t * 128 + threadIdx.x] = __float2half(z[t] * invZ);
    }
    float acc[4][4][4] = {};
    gemm_bulk<32, 3, NSTG_H>(g_attns + (size_t)((b * NTOK + tok0) >> 7) * 32 * SLAB_H,
                             g_vts   + (size_t)(b * 2 + (c0 >> 7))      * 32 * SLAB_H,
                             smem, acc, ss);
    char* dst = g_ots + ((size_t)(b * 2 + (c0 >> 7)) * 32 + (tok0 >> 5)) * SLAB_H;
    epi_t_h16(acc, smem, dst, nullptr);
}

// ---------------------------------------------------------------------------
// Stage 4: z = Wp^T o, fp16 1-term. grid (2, 8, 16)
// ---------------------------------------------------------------------------
__global__ void __launch_bounds__(NTHREADS, 2) final_kernel(float* __restrict__ z)
{
    extern __shared__ char smem[];
    int c0 = blockIdx.x * 128, p0 = blockIdx.y * 128, b = blockIdx.z;
    float acc[4][4][4] = {};
    gemm_bulk<32, 3, NSTG_H>(g_wpts + (size_t)(p0 >> 7) * 32 * SLAB_H,
                             g_ots  + (size_t)(b * 2 + (c0 >> 7)) * 32 * SLAB_H,
                             smem, acc);
    epi_f32(acc, z + ((long)b * NTOK + p0) * CDIM + c0, CDIM);
}

// ---------------------------------------------------------------------------
extern "C" void kernel_launch(void* const* d_in, const int* in_sizes, int n_in,
                              void* d_out, int out_size)
{
    const float* x  = (const float*)d_in[0];
    const float* Wq = (const float*)d_in[1];
    const float* bq = (const float*)d_in[2];
    const float* Wk = (const float*)d_in[3];
    const float* Wv = (const float*)d_in[5];
    const float* bv = (const float*)d_in[6];
    const float* Wp = (const float*)d_in[7];
    float* out = (float*)d_out;

    cudaFuncSetAttribute(proj_kernel,   cudaFuncAttributeMaxDynamicSharedMemorySize, SMEM_3T);
    cudaFuncSetAttribute(scores_kernel, cudaFuncAttributeMaxDynamicSharedMemorySize, SMEM_3T);
    cudaFuncSetAttribute(av_kernel,     cudaFuncAttributeMaxDynamicSharedMemorySize, SMEM_AV);
    cudaFuncSetAttribute(final_kernel,  cudaFuncAttributeMaxDynamicSharedMemorySize, SMEM_1T);

    prepx_kernel<<<dim3(5201), NTHREADS>>>(Wq, Wk, Wv, Wp, bq, x);         // 1
    proj_kernel  <<<dim3(2, 128, 3), NTHREADS, SMEM_3T>>>(bv, x);          // 2
    scores_kernel<<<dim3(8, 8, 16),  NTHREADS, SMEM_3T>>>();               // 3
    av_kernel    <<<dim3(2, 8, 16),  NTHREADS, SMEM_AV>>>();               // 4 <- profiled
    final_kernel <<<dim3(2, 8, 16),  NTHREADS, SMEM_1T>>>(out);            // 5
}

// round 17
// speedup vs baseline: 1.2078x; 1.0393x over previous
#include <cuda_runtime.h>
#include <cuda_bf16.h>
#include <cuda_fp16.h>
#include <cstdint>

#define BATCH 16
#define NTOK  1024
#define CDIM  256
#define NTHREADS 256
#define NSTG_F 3                        // stages for split (32KB) kernels
#define NSTG_H 4                        // stages for 1-term h16 (16KB) kernels
#define SLAB_F 16384                    // split slab: 128 rows x 128B
#define SLAB_H 8192                     // single-fp16 slab: 128 rows x 64B
#define SMEM_3T (NSTG_F*2*SLAB_F + 4096)   // ring 96KB + mbar (zsm overlays ring)
#define SMEM_AV (NSTG_H*2*SLAB_H + 4096)   // ring 64KB + mbar + ss
#define SMEM_1T (NSTG_H*2*SLAB_H + 1024)

// ---------------------------------------------------------------------------
// Split tiled format: rows in tiles of 128; tile t, k-slab s (32 k) is a
// contiguous 16KB smem image: row r at r*128, chunk cc at (cc^(r&7))*16;
// chunks 0-3 hi, 4-7 lo (addr = hi ^ 64). fp16 pairs.
// Single-fp16 format: 8KB slabs, row r at r*64, chunk cc at (cc^((r>>1)&3))*16.
// ---------------------------------------------------------------------------
__device__ __align__(128) char g_xs  [16384*1024];      // x    fp16 split
__device__ __align__(128) char g_wvs [256*1024];        // Wv   fp16 split
__device__ __align__(128) char g_mts [256*1024];        // Mt = (Wq^T Wk)^T [e][c], fp16 split
__device__ __align__(128) char g_qms [16384*1024];      // qm = x·M, fp16 split
__device__ __align__(128) char g_vts [16*256*2048];     // v^T  fp16 single
__device__ __align__(128) char g_ots [16*256*2048];     // o^T  fp16 single
__device__ __align__(128) char g_attns[(size_t)16384*2048]; // attn_norm fp16 single
__device__ __align__(128) char g_wpts[1024*2048];       // Wp^T fp16 single
__device__ float g_zp[BATCH*8*NTOK];                    // per (b, n-tile, tok) exp sums
__device__ float g_w[BATCH*NTOK];                       // w_j = x_j . (Wk^T bq)
__device__ float g_beta[256];
__device__ float g_zero[256];

// ---------------------------------------------------------------------------
__device__ __forceinline__ uint32_t smem_u32(const void* p){
    uint32_t a;
    asm("{ .reg .u64 t; cvta.to.shared.u64 t, %1; cvt.u32.u64 %0, t; }" : "=r"(a) : "l"(p));
    return a;
}
__device__ __forceinline__ void ldsm4(uint32_t* r, uint32_t addr){
    asm volatile("ldmatrix.sync.aligned.m8n8.x4.shared.b16 {%0,%1,%2,%3}, [%4];"
        : "=r"(r[0]), "=r"(r[1]), "=r"(r[2]), "=r"(r[3]) : "r"(addr));
}
__device__ __forceinline__ void mma_f16(float* d, const uint32_t* a, const uint32_t* b){
    asm volatile("mma.sync.aligned.m16n8k16.row.col.f32.f16.f16.f32 "
        "{%0,%1,%2,%3}, {%4,%5,%6,%7}, {%8,%9}, {%0,%1,%2,%3};"
        : "+f"(d[0]), "+f"(d[1]), "+f"(d[2]), "+f"(d[3])
        : "r"(a[0]), "r"(a[1]), "r"(a[2]), "r"(a[3]), "r"(b[0]), "r"(b[1]));
}
__device__ __forceinline__ void split2h(float v0, float v1, __half2& h, __half2& l){
    h = __floats2half2_rn(v0, v1);
    l = __floats2half2_rn(v0 - __half2float(__low2half(h)),
                          v1 - __half2float(__high2half(h)));
}
template<class T> __device__ __forceinline__ uint32_t b2u(T v){
    uint32_t u; memcpy(&u, &v, 4); return u;
}
template<class T> __device__ __forceinline__ uint16_t b2s(T v){
    uint16_t u; memcpy(&u, &v, 2); return u;
}
__device__ __forceinline__ uint32_t h2mul(uint32_t a, uint32_t s){
    __half2 x, y; memcpy(&x, &a, 4); memcpy(&y, &s, 4);
    __half2 r = __hmul2(x, y); uint32_t u; memcpy(&u, &r, 4); return u;
}

// global tiled-format offsets (producers)
__device__ __forceinline__ size_t sbf_off(long tile, int nslab, int r, int k){
    int cc = (k & 31) >> 3;
    return ((size_t)(tile * nslab + (k >> 5)) << 14)
         + (size_t)(r * 128) + (size_t)(((cc ^ (r & 7)) << 4) + (k & 7) * 2);
}
__device__ __forceinline__ size_t h16_off(long tile, int nslab, int r, int k){
    int cc = (k & 31) >> 3;
    return ((size_t)(tile * nslab + (k >> 5)) << 13)
         + (size_t)(r * 64) + (size_t)(((cc ^ ((r >> 1) & 3)) << 4) + (k & 7) * 2);
}
// local (within stage region) offsets
__device__ __forceinline__ int loc_f(int r, int k){
    int cc = (k & 31) >> 3;
    return ((k >> 5) << 14) + r * 128 + ((cc ^ (r & 7)) << 4) + (k & 7) * 2;
}
__device__ __forceinline__ int loc_h(int r, int k){
    int cc = (k & 31) >> 3;
    return ((k >> 5) << 13) + r * 64 + ((cc ^ ((r >> 1) & 3)) << 4) + (k & 7) * 2;
}

#define MBAR_INIT(mb,c)  asm volatile("mbarrier.init.shared.b64 [%0], %1;" :: "r"(mb), "r"((uint32_t)(c)) : "memory")
#define MBAR_EXPECT(mb,n) asm volatile("mbarrier.arrive.expect_tx.shared.b64 _, [%0], %1;" :: "r"(mb), "r"((uint32_t)(n)) : "memory")
#define MBAR_ARRIVE(mb)  asm volatile("mbarrier.arrive.shared.b64 _, [%0];" :: "r"(mb) : "memory")
#define BULK_G2S(dst,src,n,mb) asm volatile("cp.async.bulk.shared::cta.global.mbarrier::complete_tx::bytes [%0], [%1], %2, [%3];" :: "r"(dst), "l"(src), "r"((uint32_t)(n)), "r"(mb) : "memory")
#define BULK_S2G(dst,src,n) asm volatile("cp.async.bulk.global.shared::cta.bulk_group [%0], [%1], %2;" :: "l"(dst), "r"(src), "r"((uint32_t)(n)) : "memory")
#define BULK_COMMIT() asm volatile("cp.async.bulk.commit_group;" ::: "memory")
#define BULK_WAIT0()  asm volatile("cp.async.bulk.wait_group 0;" ::: "memory")
#define FENCE_ASYNC() asm volatile("fence.proxy.async.shared::cta;" ::: "memory")

#define MBAR_WAIT(mb, par) do { \
    uint32_t _m = (uint32_t)(mb), _p = (uint32_t)(par), _d; \
    asm volatile("{\n\t.reg .pred p;\n\t" \
        "mbarrier.try_wait.parity.acquire.cta.shared::cta.b64 p, [%1], %2;\n\t" \
        "selp.b32 %0, 1, 0, p;\n\t}" : "=r"(_d) : "r"(_m), "r"(_p) : "memory"); \
    if (!_d) { \
        asm volatile("{\n\t.reg .pred P1;\n\t" \
            "WL_%=:\n\t" \
            "mbarrier.try_wait.parity.acquire.cta.shared::cta.b64 P1, [%0], %1, 0x989680;\n\t" \
            "@P1 bra.uni WD_%=;\n\t" \
            "bra.uni WL_%=;\n\t" \
            "WD_%=:\n\t}" :: "r"(_m), "r"(_p) : "memory"); \
    } \
} while(0)

// ---------------------------------------------------------------------------
// 3-term fp16 compute (split A, split B). CTA 128x128, warps 2(M)x4(N).
// ---------------------------------------------------------------------------
__device__ __forceinline__ void compute_slab3(char* buf, float acc[4][4][4])
{
    int tid = threadIdx.x, lane = tid & 31, wid = tid >> 5;
    uint32_t sA = smem_u32(buf), sB = sA + SLAB_F;
    int mw = (wid & 1) * 64, nw = (wid >> 1) * 32;
    int arow = lane & 15, ahalf = lane >> 4;
    int brow = (lane & 7) + ((lane >> 4) & 1) * 8, bhalf = (lane >> 3) & 1;

#pragma unroll
    for (int ks = 0; ks < 2; ++ks) {
        uint32_t bh[8], bl[8];
#pragma unroll
        for (int nj = 0; nj < 2; ++nj) {
            int r = nw + nj * 16 + brow;
            int c = ks * 2 + bhalf;
            ldsm4(bh + nj * 4, sB + r * 128 + (((c    ) ^ (r & 7)) << 4));
            ldsm4(bl + nj * 4, sB + r * 128 + (((c + 4) ^ (r & 7)) << 4));
        }
#pragma unroll
        for (int mi = 0; mi < 4; ++mi) {
            int r = mw + mi * 16 + arow;
            int c = ks * 2 + ahalf;
            uint32_t ah[4], al[4];
            ldsm4(ah, sA + r * 128 + (((c    ) ^ (r & 7)) << 4));
            ldsm4(al, sA + r * 128 + (((c + 4) ^ (r & 7)) << 4));
#pragma unroll
            for (int j = 0; j < 4; ++j) {
                const uint32_t* bhf = &bh[(j >> 1) * 4 + (j & 1) * 2];
                const uint32_t* blf = &bl[(j >> 1) * 4 + (j & 1) * 2];
                float* d = acc[mi][j];
                mma_f16(d, ah, bhf);
                mma_f16(d, al, bhf);
                mma_f16(d, ah, blf);
            }
        }
    }
}

// ---------------------------------------------------------------------------
// 1-term fp16 on SPLIT layout (reads hi chunks only; lo bytes ignored).
// ---------------------------------------------------------------------------
__device__ __forceinline__ void compute_slab1f(char* buf, float acc[4][4][4])
{
    int tid = threadIdx.x, lane = tid & 31, wid = tid >> 5;
    uint32_t sA = smem_u32(buf), sB = sA + SLAB_F;
    int mw = (wid & 1) * 64, nw = (wid >> 1) * 32;
    int arow = lane & 15, ahalf = lane >> 4;
    int brow = (lane & 7) + ((lane >> 4) & 1) * 8, bhalf = (lane >> 3) & 1;

#pragma unroll
    for (int ks = 0; ks < 2; ++ks) {
        uint32_t bh[8];
#pragma unroll
        for (int nj = 0; nj < 2; ++nj) {
            int r = nw + nj * 16 + brow;
            int c = ks * 2 + bhalf;
            ldsm4(bh + nj * 4, sB + r * 128 + ((c ^ (r & 7)) << 4));
        }
#pragma unroll
        for (int mi = 0; mi < 4; ++mi) {
            int r = mw + mi * 16 + arow;
            int c = ks * 2 + ahalf;
            uint32_t ah[4];
            ldsm4(ah, sA + r * 128 + ((c ^ (r & 7)) << 4));
#pragma unroll
            for (int j = 0; j < 4; ++j)
                mma_f16(acc[mi][j], ah, &bh[(j >> 1) * 4 + (j & 1) * 2]);
        }
    }
}

// ---------------------------------------------------------------------------
// 1-term fp16 compute (single A, single B; 64B rows). Optional A-frag scale.
// ---------------------------------------------------------------------------
template<bool SCALE>
__device__ __forceinline__ void compute_slab1(char* buf, float acc[4][4][4],
        const __half* __restrict__ ss)
{
    int tid = threadIdx.x, lane = tid & 31, wid = tid >> 5;
    uint32_t sA = smem_u32(buf), sB = sA + SLAB_H;
    int mw = (wid & 1) * 64, nw = (wid >> 1) * 32;
    int arow = lane & 15, ahalf = lane >> 4;
    int brow = (lane & 7) + ((lane >> 4) & 1) * 8, bhalf = (lane >> 3) & 1;
    int r0 = lane >> 2;

    uint32_t sv0[4], sv1[4];
    if (SCALE) {
#pragma unroll
        for (int mi = 0; mi < 4; ++mi) {
            int rr = mw + mi * 16 + r0;
            sv0[mi] = b2u(__half2half2(ss[rr]));
            sv1[mi] = b2u(__half2half2(ss[rr + 8]));
        }
    }

#pragma unroll
    for (int ks = 0; ks < 2; ++ks) {
        uint32_t bh[8];
#pragma unroll
        for (int nj = 0; nj < 2; ++nj) {
            int r = nw + nj * 16 + brow;
            int c = ks * 2 + bhalf;
            ldsm4(bh + nj * 4, sB + r * 64 + ((c ^ ((r >> 1) & 3)) << 4));
        }
#pragma unroll
        for (int mi = 0; mi < 4; ++mi) {
            int r = mw + mi * 16 + arow;
            int c = ks * 2 + ahalf;
            uint32_t ah[4];
            ldsm4(ah, sA + r * 64 + ((c ^ ((r >> 1) & 3)) << 4));
            if (SCALE) {
                ah[0] = h2mul(ah[0], sv0[mi]);
                ah[2] = h2mul(ah[2], sv0[mi]);
                ah[1] = h2mul(ah[1], sv1[mi]);
                ah[3] = h2mul(ah[3], sv1[mi]);
            }
#pragma unroll
            for (int j = 0; j < 4; ++j)
                mma_f16(acc[mi][j], ah, &bh[(j >> 1) * 4 + (j & 1) * 2]);
        }
    }
}

// ---------------------------------------------------------------------------
// Bulk-copy mainloop with full/empty mbarrier pipeline (no per-slab
// __syncthreads). full[s]: tx-completion (count 1). empty[s]: 8 warp arrivals.
// Producer (tid 0) waits empty[sn] before refilling stage sn; each warp
// arrives empty[s] after computing slab s (release orders its reads).
// MODE 1: 3-term split; MODE 2: 1-term split; MODE 3: 1-term h16.
// ---------------------------------------------------------------------------
template<int NC, int MODE, int NST>
__device__ __forceinline__ void gemm_bulk(const char* __restrict__ A,
                                          const char* __restrict__ B,
                                          char* smem, float acc[4][4][4],
                                          const __half* __restrict__ ss = nullptr)
{
    constexpr int SL  = (MODE == 3) ? SLAB_H : SLAB_F;
    constexpr int STG = 2 * SL;
    uint32_t mbf = smem_u32(smem + NST * STG);          // full barriers
    uint32_t mbe = mbf + 8 * NST;                       // empty barriers
    int tid = threadIdx.x;
    if (tid == 0) {
#pragma unroll
        for (int s = 0; s < NST; ++s) { MBAR_INIT(mbf + 8 * s, 1); MBAR_INIT(mbe + 8 * s, 8); }
        FENCE_ASYNC();
    }
    __syncthreads();
    if (tid == 0) {
#pragma unroll
        for (int s = 0; s < NST - 1; ++s) {
            uint32_t m = mbf + 8 * s;
            uint32_t d = smem_u32(smem + s * STG);
            MBAR_EXPECT(m, STG);
            BULK_G2S(d,      A + (size_t)s * SL, SL, m);
            BULK_G2S(d + SL, B + (size_t)s * SL, SL, m);
        }
    }
#pragma unroll 4
    for (int c = 0; c < NC; ++c) {
        int s = c % NST;
        MBAR_WAIT(mbf + 8 * s, (c / NST) & 1);
        int nc = c + NST - 1;
        if (tid == 0 && nc < NC) {
            int sn = nc % NST;
            if (nc >= NST) MBAR_WAIT(mbe + 8 * sn, ((nc / NST) - 1) & 1);
            uint32_t m = mbf + 8 * sn;
            uint32_t d = smem_u32(smem + sn * STG);
            MBAR_EXPECT(m, STG);
            BULK_G2S(d,      A + (size_t)nc * SL, SL, m);
            BULK_G2S(d + SL, B + (size_t)nc * SL, SL, m);
        }
        if (MODE == 3) {
            if (ss) compute_slab1<true >(smem + s * STG, acc, ss + (c >> 2) * 128);
            else    compute_slab1<false>(smem + s * STG, acc, nullptr);
        } else if (MODE == 2) {
            compute_slab1f(smem + s * STG, acc);
        } else {
            compute_slab3(smem + s * STG, acc);
        }
        if ((tid & 31) == 0) MBAR_ARRIVE(mbe + 8 * s);
    }
}

// drain a staged 4-slab region to global
template<int SL>
__device__ __forceinline__ void stage_drain(char* smem, char* dst)
{
    __syncthreads();
    if (threadIdx.x == 0) {
        FENCE_ASYNC();
#pragma unroll
        for (int sl = 0; sl < 4; ++sl)
            BULK_S2G(dst + sl * SL, smem_u32(smem + sl * SL), SL);
        BULK_COMMIT();
        BULK_WAIT0();
    }
}

// ---------------------------------------------------------------------------
// Epilogues. Frag: d0,d1 -> (row=lane>>2, col=(lane&3)*2+e), d2,d3 row+8.
// ---------------------------------------------------------------------------
__device__ __forceinline__ void epi_f32(const float acc[4][4][4],
        float* __restrict__ Cg, int ldc)
{
    int tid = threadIdx.x, lane = tid & 31, wid = tid >> 5;
    int row0 = (wid & 1) * 64 + (lane >> 2), col0 = (wid >> 1) * 32 + (lane & 3) * 2;
#pragma unroll
    for (int mi = 0; mi < 4; ++mi)
#pragma unroll
        for (int j = 0; j < 4; ++j) {
            int c = col0 + j * 8;
#pragma unroll
            for (int h = 0; h < 2; ++h) {
                int r = row0 + mi * 16 + h * 8;
                *reinterpret_cast<float2*>(Cg + (long)r * ldc + c) =
                    make_float2(acc[mi][j][h * 2], acc[mi][j][h * 2 + 1]);
            }
        }
}

// qm: fp16 split normal; 64KB stage at smem base.
__device__ __forceinline__ void epi_split_h(const float acc[4][4][4],
        char* smem, char* dst, const float* __restrict__ bias)
{
    int tid = threadIdx.x, lane = tid & 31, wid = tid >> 5;
    int rw0 = (wid & 1) * 64 + (lane >> 2), cw0 = (wid >> 1) * 32 + (lane & 3) * 2;
    __syncthreads();
#pragma unroll
    for (int mi = 0; mi < 4; ++mi)
#pragma unroll
        for (int j = 0; j < 4; ++j) {
            int c = cw0 + j * 8;
            float b0 = bias[c], b1 = bias[c + 1];
#pragma unroll
            for (int h = 0; h < 2; ++h) {
                int r = rw0 + mi * 16 + h * 8;
                __half2 hh, ll;
                split2h(acc[mi][j][h * 2] + b0, acc[mi][j][h * 2 + 1] + b1, hh, ll);
                int off = loc_f(r, c);
                *reinterpret_cast<uint32_t*>(smem + off)        = b2u(hh);
                *reinterpret_cast<uint32_t*>(smem + (off ^ 64)) = b2u(ll);
            }
        }
    stage_drain<SLAB_F>(smem, dst);
}

// transposed single-fp16 (v^T with bias, o^T without); 32KB stage.
__device__ __forceinline__ void epi_t_h16(const float acc[4][4][4],
        char* smem, char* dst, const float* __restrict__ bias)
{
    int tid = threadIdx.x, lane = tid & 31, wid = tid >> 5;
    int rw0 = (wid & 1) * 64 + (lane >> 2), cw0 = (wid >> 1) * 32 + (lane & 3) * 2;
    __syncthreads();
#pragma unroll
    for (int mi = 0; mi < 4; ++mi)
#pragma unroll
        for (int j = 0; j < 4; ++j)
#pragma unroll
            for (int h = 0; h < 2; ++h) {
                int m = rw0 + mi * 16 + h * 8;
#pragma unroll
                for (int e = 0; e < 2; ++e) {
                    int n = cw0 + j * 8 + e;
                    float v = acc[mi][j][h * 2 + e] + (bias ? bias[n] : 0.0f);
                    *reinterpret_cast<uint16_t*>(smem + loc_h(n, m)) = b2s(__float2half(v));
                }
            }
    stage_drain<SLAB_H>(smem, dst);
}

// attn: exp(acc + w_col), per-tile normalize, single fp16 + partial sums.
// Stage 32KB at smem base; zsm overlays ring at +32KB (ring is drained here).
__device__ __forceinline__ void epi_attn(const float acc[4][4][4], char* smem,
        char* dst, const float* __restrict__ wcol, float* __restrict__ zp_out)
{
    int tid = threadIdx.x, lane = tid & 31, wid = tid >> 5;
    int rw0 = (wid & 1) * 64 + (lane >> 2), cw0 = (wid >> 1) * 32 + (lane & 3) * 2;
    float* zsm = reinterpret_cast<float*>(smem + 4 * SLAB_H);
    __syncthreads();

    float wc[8];
#pragma unroll
    for (int j = 0; j < 4; ++j) {
        wc[j * 2]     = wcol[cw0 + j * 8];
        wc[j * 2 + 1] = wcol[cw0 + j * 8 + 1];
    }

    float ex[4][4][4];
#pragma unroll
    for (int mi = 0; mi < 4; ++mi) {
#pragma unroll
        for (int h = 0; h < 2; ++h) {
            int r = rw0 + mi * 16 + h * 8;
            float rs = 0.0f;
#pragma unroll
            for (int j = 0; j < 4; ++j) {
                float e0 = __expf(acc[mi][j][h * 2]     + wc[j * 2]);
                float e1 = __expf(acc[mi][j][h * 2 + 1] + wc[j * 2 + 1]);
                ex[mi][j][h * 2] = e0; ex[mi][j][h * 2 + 1] = e1;
                rs += e0 + e1;
            }
            rs += __shfl_xor_sync(0xffffffffu, rs, 1);
            rs += __shfl_xor_sync(0xffffffffu, rs, 2);
            if ((lane & 3) == 0)
                zsm[(wid >> 1) * 128 + r] = rs;
        }
    }
    __syncthreads();
    if (tid < 128)
        zp_out[tid] = zsm[tid] + zsm[128 + tid] + zsm[256 + tid] + zsm[384 + tid];
#pragma unroll
    for (int mi = 0; mi < 4; ++mi)
#pragma unroll
        for (int h = 0; h < 2; ++h) {
            int r = rw0 + mi * 16 + h * 8;
            float inv = 1.0f / (zsm[r] + zsm[128 + r] + zsm[256 + r] + zsm[384 + r]);
#pragma unroll
            for (int j = 0; j < 4; ++j) {
                int c = cw0 + j * 8;
                __half2 hv = __floats2half2_rn(ex[mi][j][h * 2] * inv,
                                               ex[mi][j][h * 2 + 1] * inv);
                *reinterpret_cast<uint32_t*>(smem + loc_h(r, c)) = b2u(hv);
            }
        }
    stage_drain<SLAB_H>(smem, dst);
}

// ---------------------------------------------------------------------------
// Prep+xconv fused: Wv (0..63) | Wp^T (64..1087) | Mt (1088..1103) |
//                   beta (1104) | x conv (1105..5200)
// ---------------------------------------------------------------------------
__global__ void __launch_bounds__(NTHREADS) prepx_kernel(
        const float* __restrict__ Wq, const float* __restrict__ Wk,
        const float* __restrict__ Wv, const float* __restrict__ Wp,
        const float* __restrict__ bq, const float* __restrict__ x)
{
    int bid = blockIdx.x, tid = threadIdx.x;
    if (bid < 64) {
        long i = (long)bid * NTHREADS + tid;
        float4 v = reinterpret_cast<const float4*>(Wv)[i];
        long e = i * 4;
        int r = (int)(e >> 8), k = (int)(e & 255);
        size_t off = sbf_off(r >> 7, 8, r & 127, k);
        __half2 h0, l0, h1, l1;
        split2h(v.x, v.y, h0, l0);
        split2h(v.z, v.w, h1, l1);
        *reinterpret_cast<uint2*>(g_wvs + off)        = make_uint2(b2u(h0), b2u(h1));
        *reinterpret_cast<uint2*>(g_wvs + (off ^ 64)) = make_uint2(b2u(l0), b2u(l1));
    } else if (bid < 1088) {
        __shared__ float t[32][33];
        int b2 = bid - 64;
        int h = b2 >> 5, n0 = (b2 & 31) * 32;
        int tx = tid & 31, ty = tid >> 5;
        const float* src = Wp + (long)h * 32768 + (long)n0 * 32;
#pragma unroll
        for (int i = 0; i < 4; ++i) t[ty + i * 8][tx] = src[(ty + i * 8) * 32 + tx];
        __syncthreads();
#pragma unroll
        for (int i = 0; i < 4; ++i) {
            int w = ty + i * 8;
            int p = h * 32 + w, n = n0 + tx;
            *reinterpret_cast<uint16_t*>(g_wpts + h16_off(p >> 7, 32, p & 127, n)) =
                b2s(__float2half(t[tx][w]));
        }
    } else if (bid < 1104) {
        __shared__ float As[32][64], Bs[32][64];
        int mt = bid - 1088;
        int e0 = (mt >> 2) * 64, c0 = (mt & 3) * 64;
        int tx = tid & 15, ty = tid >> 4;
        float acc[4][4] = {};
        for (int k0 = 0; k0 < 256; k0 += 32) {
            for (int i = tid; i < 2048; i += NTHREADS) {
                int dd = i >> 6, ee = i & 63;
                As[dd][ee] = Wk[(long)(k0 + dd) * 256 + e0 + ee];
                Bs[dd][ee] = Wq[(long)(k0 + dd) * 256 + c0 + ee];
            }
            __syncthreads();
#pragma unroll 8
            for (int dd = 0; dd < 32; ++dd) {
                float a[4], b[4];
#pragma unroll
                for (int i = 0; i < 4; ++i) { a[i] = As[dd][ty * 4 + i]; b[i] = Bs[dd][tx * 4 + i]; }
#pragma unroll
                for (int i = 0; i < 4; ++i)
#pragma unroll
                    for (int j = 0; j < 4; ++j) acc[i][j] += a[i] * b[j];
            }
            __syncthreads();
        }
#pragma unroll
        for (int i = 0; i < 4; ++i)
#pragma unroll
            for (int j = 0; j < 4; ++j) {
                int e = e0 + ty * 4 + i, c = c0 + tx * 4 + j;
                __half hb = __float2half(acc[i][j]);
                __half lb = __float2half(acc[i][j] - __half2float(hb));
                size_t off = sbf_off(e >> 7, 8, e & 127, c);
                *reinterpret_cast<uint16_t*>(g_mts + off)        = b2s(hb);
                *reinterpret_cast<uint16_t*>(g_mts + (off ^ 64)) = b2s(lb);
            }
    } else if (bid == 1104) {
        int c = tid;
        float acc = 0.0f;
        for (int d = 0; d < 256; ++d) acc += Wk[(long)d * 256 + c] * bq[d];
        g_beta[c] = acc;
    } else {
        long i = (long)(bid - 1105) * NTHREADS + tid;
        float4 v = reinterpret_cast<const float4*>(x)[i];
        long e = i * 4;
        int r = (int)(e >> 8), k = (int)(e & 255);
        size_t off = sbf_off(r >> 7, 8, r & 127, k);
        __half2 h0, l0, h1, l1;
        split2h(v.x, v.y, h0, l0);
        split2h(v.z, v.w, h1, l1);
        *reinterpret_cast<uint2*>(g_xs + off)        = make_uint2(b2u(h0), b2u(h1));
        *reinterpret_cast<uint2*>(g_xs + (off ^ 64)) = make_uint2(b2u(l0), b2u(l1));
    }
}

// ---------------------------------------------------------------------------
// Stage 1: proj. grid (2, 128, 3): sel0 qm (3-term), sel1 v (1-term split),
// sel2 w-vector (blockIdx.x==0 only).
// ---------------------------------------------------------------------------
__global__ void __launch_bounds__(NTHREADS, 2)
proj_kernel(const float* __restrict__ bv, const float* __restrict__ x)
{
    extern __shared__ char smem[];
    int n0 = blockIdx.x * 128; long m0 = (long)blockIdx.y * 128; int sel = blockIdx.z;
    if (sel == 2) {
        if (blockIdx.x != 0) return;
        int lane = threadIdx.x & 31, wrp = threadIdx.x >> 5;
#pragma unroll
        for (int rr = wrp; rr < 128; rr += 8) {
            const float* row = x + (m0 + rr) * 256;
            float p = 0.0f;
#pragma unroll
            for (int e = 0; e < 8; ++e)
                p += row[lane + e * 32] * g_beta[lane + e * 32];
#pragma unroll
            for (int o = 16; o; o >>= 1) p += __shfl_xor_sync(0xffffffffu, p, o);
            if (!lane) g_w[m0 + rr] = p;
        }
        return;
    }
    float acc[4][4][4] = {};
    if (sel == 0) {
        gemm_bulk<8, 1, NSTG_F>(g_xs + (m0 >> 7) * 8 * SLAB_F,
                                g_mts + (size_t)(n0 >> 7) * 8 * SLAB_F, smem, acc);
        char* dst = g_qms + ((size_t)(m0 >> 7) * 8 + (n0 >> 5)) * SLAB_F;
        epi_split_h(acc, smem, dst, g_zero + n0);
    } else {
        gemm_bulk<8, 2, NSTG_F>(g_xs + (m0 >> 7) * 8 * SLAB_F,
                                g_wvs + (size_t)(n0 >> 7) * 8 * SLAB_F, smem, acc);
        int b = (int)(m0 >> 10), tok0 = (int)(m0 & 1023);
        char* dst = g_vts + ((size_t)(b * 2 + (n0 >> 7)) * 32 + (tok0 >> 5)) * SLAB_H;
        epi_t_h16(acc, smem, dst, bv + n0);
    }
}

// ---------------------------------------------------------------------------
// Stage 2: attn_norm = exp(qm x^T + w_j)/zp_tile, fp16 3-term. grid (8, 8, 16)
// ---------------------------------------------------------------------------
__global__ void __launch_bounds__(NTHREADS, 2) scores_kernel()
{
    extern __shared__ char smem[];
    int n0 = blockIdx.x * 128, m0 = blockIdx.y * 128, b = blockIdx.z;
    float acc[4][4][4] = {};
    gemm_bulk<8, 1, NSTG_F>(g_qms + (size_t)((b * NTOK + m0) >> 7) * 8 * SLAB_F,
                            g_xs  + (size_t)((b * NTOK + n0) >> 7) * 8 * SLAB_F,
                            smem, acc);
    char* dst = g_attns + ((size_t)((b * NTOK + m0) >> 7) * 32 + (n0 >> 5)) * SLAB_H;
    epi_attn(acc, smem, dst, g_w + (long)b * NTOK + n0,
             g_zp + ((long)b * 8 + blockIdx.x) * NTOK + m0);
}

// ---------------------------------------------------------------------------
// Stage 3: o^T, fp16 1-term with per-tile A rescale. grid (2, 8, 16)
// ---------------------------------------------------------------------------
__global__ void __launch_bounds__(NTHREADS, 2) av_kernel()
{
    extern __shared__ char smem[];
    int c0 = blockIdx.x * 128, tok0 = blockIdx.y * 128, b = blockIdx.z;
    __half* ss = reinterpret_cast<__half*>(smem + NSTG_H * 2 * SLAB_H + 128);
    if (threadIdx.x < 128) {
        float z[8], Z = 0.0f;
#pragma unroll
        for (int t = 0; t < 8; ++t) {
            z[t] = g_zp[((long)b * 8 + t) * NTOK + tok0 + threadIdx.x];
            Z += z[t];
        }
        float invZ = 1.0f / Z;
#pragma unroll
        for (int t = 0; t < 8; ++t)
            ss[t * 128 + threadIdx.x] = __float2half(z[t] * invZ);
    }
    float acc[4][4][4] = {};
    gemm_bulk<32, 3, NSTG_H>(g_attns + (size_t)((b * NTOK + tok0) >> 7) * 32 * SLAB_H,
                             g_vts   + (size_t)(b * 2 + (c0 >> 7))      * 32 * SLAB_H,
                             smem, acc, ss);
    char* dst = g_ots + ((size_t)(b * 2 + (c0 >> 7)) * 32 + (tok0 >> 5)) * SLAB_H;
    epi_t_h16(acc, smem, dst, nullptr);
}

// ---------------------------------------------------------------------------
// Stage 4: z = Wp^T o, fp16 1-term. grid (2, 8, 16)
// ---------------------------------------------------------------------------
__global__ void __launch_bounds__(NTHREADS, 2) final_kernel(float* __restrict__ z)
{
    extern __shared__ char smem[];
    int c0 = blockIdx.x * 128, p0 = blockIdx.y * 128, b = blockIdx.z;
    float acc[4][4][4] = {};
    gemm_bulk<32, 3, NSTG_H>(g_wpts + (size_t)(p0 >> 7) * 32 * SLAB_H,
                             g_ots  + (size_t)(b * 2 + (c0 >> 7)) * 32 * SLAB_H,
                             smem, acc);
    epi_f32(acc, z + ((long)b * NTOK + p0) * CDIM + c0, CDIM);
}

// ---------------------------------------------------------------------------
extern "C" void kernel_launch(void* const* d_in, const int* in_sizes, int n_in,
                              void* d_out, int out_size)
{
    const float* x  = (const float*)d_in[0];
    const float* Wq = (const float*)d_in[1];
    const float* bq = (const float*)d_in[2];
    const float* Wk = (const float*)d_in[3];
    const float* Wv = (const float*)d_in[5];
    const float* bv = (const float*)d_in[6];
    const float* Wp = (const float*)d_in[7];
    float* out = (float*)d_out;

    cudaFuncSetAttribute(proj_kernel,   cudaFuncAttributeMaxDynamicSharedMemorySize, SMEM_3T);
    cudaFuncSetAttribute(scores_kernel, cudaFuncAttributeMaxDynamicSharedMemorySize, SMEM_3T);
    cudaFuncSetAttribute(av_kernel,     cudaFuncAttributeMaxDynamicSharedMemorySize, SMEM_AV);
    cudaFuncSetAttribute(final_kernel,  cudaFuncAttributeMaxDynamicSharedMemorySize, SMEM_1T);

    prepx_kernel<<<dim3(5201), NTHREADS>>>(Wq, Wk, Wv, Wp, bq, x);         // 1
    proj_kernel  <<<dim3(2, 128, 3), NTHREADS, SMEM_3T>>>(bv, x);          // 2
    scores_kernel<<<dim3(8, 8, 16),  NTHREADS, SMEM_3T>>>();               // 3
    av_kernel    <<<dim3(2, 8, 16),  NTHREADS, SMEM_AV>>>();               // 4 <- profiled
    final_kernel <<<dim3(2, 8, 16),  NTHREADS, SMEM_1T>>>(out);            // 5
}